// round 1
// baseline (speedup 1.0000x reference)
#include <cuda_runtime.h>
#include <cuda_bf16.h>
#include <math.h>

// Problem constants
#define BB 2
#define SS 1024
#define DD 1024
#define HH 16
#define LL 3
#define FFF 4096
#define VV 32000
#define DK 64
#define MTOK (BB*SS)   // 2048 tokens

// ---------------------------------------------------------------------------
// Scratch (allocation-free: __device__ globals)
// ---------------------------------------------------------------------------
__device__ float g_h[MTOK * DD];        // hidden state          8 MB
__device__ float g_q[MTOK * DD];        // Q                     8 MB
__device__ float g_k[MTOK * DD];        // K                     8 MB
__device__ float g_v[MTOK * DD];        // V                     8 MB
__device__ float g_attn[MTOK * DD];     // attention concat out  8 MB
__device__ float g_t2[MTOK * DD];       // proj / ffn2 out       8 MB
__device__ float g_t1[MTOK * FFF];      // ffn intermediate     32 MB
__device__ float g_scores[(size_t)BB * HH * SS * SS]; // 134 MB

// ---------------------------------------------------------------------------
// Embedding: h = emb[x] + 0.05 * noise
// ---------------------------------------------------------------------------
__global__ void embed_kernel(const int* __restrict__ x,
                             const float* __restrict__ noise,
                             const float* __restrict__ emb,
                             float* __restrict__ h)
{
    size_t idx = (size_t)blockIdx.x * blockDim.x + threadIdx.x; // over 2048*1024
    size_t tok = idx >> 10;
    int d = (int)(idx & 1023);
    h[idx] = emb[(size_t)x[tok] * DD + d] + noise[idx] * 0.05f;
}

// ---------------------------------------------------------------------------
// Generic SGEMM: C[M,N] = A[M,K] @ B[K,N] + bias[N], optional ReLU.
// 128x128 tile, BK=16, 256 threads, 8x8 microtile. Requires M%128==0,
// N%128==0, K%16==0 (true for every GEMM in this problem).
// ---------------------------------------------------------------------------
__global__ __launch_bounds__(256, 2)
void sgemm128(const float* __restrict__ A, const float* __restrict__ B,
              const float* __restrict__ bias, float* __restrict__ C,
              int M, int N, int K, int relu)
{
    __shared__ float As[16][128];
    __shared__ float Bs[16][128];
    const int tid = threadIdx.x;
    const int bm = blockIdx.y * 128;
    const int bn = blockIdx.x * 128;

    const int arow = tid >> 2;         // 0..63
    const int acol = (tid & 3) << 2;   // 0,4,8,12
    const int brow = tid >> 5;         // 0..7
    const int bcol = (tid & 31) << 2;  // 0..124
    const int tx = tid & 15, ty = tid >> 4;

    float acc[8][8];
#pragma unroll
    for (int i = 0; i < 8; i++)
#pragma unroll
        for (int j = 0; j < 8; j++) acc[i][j] = 0.f;

    for (int k0 = 0; k0 < K; k0 += 16) {
#pragma unroll
        for (int r = 0; r < 2; r++) {
            float4 v = *(const float4*)(A + (size_t)(bm + arow + r * 64) * K + k0 + acol);
            As[acol + 0][arow + r * 64] = v.x;
            As[acol + 1][arow + r * 64] = v.y;
            As[acol + 2][arow + r * 64] = v.z;
            As[acol + 3][arow + r * 64] = v.w;
        }
#pragma unroll
        for (int r = 0; r < 2; r++) {
            float4 v = *(const float4*)(B + (size_t)(k0 + brow + r * 8) * N + bn + bcol);
            *(float4*)(&Bs[brow + r * 8][bcol]) = v;
        }
        __syncthreads();
#pragma unroll
        for (int k = 0; k < 16; k++) {
            float4 a0 = *(const float4*)(&As[k][ty * 8]);
            float4 a1 = *(const float4*)(&As[k][ty * 8 + 4]);
            float4 b0 = *(const float4*)(&Bs[k][tx * 8]);
            float4 b1 = *(const float4*)(&Bs[k][tx * 8 + 4]);
            float a[8] = {a0.x, a0.y, a0.z, a0.w, a1.x, a1.y, a1.z, a1.w};
            float b[8] = {b0.x, b0.y, b0.z, b0.w, b1.x, b1.y, b1.z, b1.w};
#pragma unroll
            for (int i = 0; i < 8; i++)
#pragma unroll
                for (int j = 0; j < 8; j++)
                    acc[i][j] = fmaf(a[i], b[j], acc[i][j]);
        }
        __syncthreads();
    }

#pragma unroll
    for (int i = 0; i < 8; i++) {
        int row = bm + ty * 8 + i;
#pragma unroll
        for (int j = 0; j < 8; j += 4) {
            int col = bn + tx * 8 + j;
            float4 v;
            v.x = acc[i][j + 0] + bias[col + 0];
            v.y = acc[i][j + 1] + bias[col + 1];
            v.z = acc[i][j + 2] + bias[col + 2];
            v.w = acc[i][j + 3] + bias[col + 3];
            if (relu) {
                v.x = fmaxf(v.x, 0.f); v.y = fmaxf(v.y, 0.f);
                v.z = fmaxf(v.z, 0.f); v.w = fmaxf(v.w, 0.f);
            }
            *(float4*)(C + (size_t)row * N + col) = v;
        }
    }
}

// ---------------------------------------------------------------------------
// Attention scores: per (b,h): S = scale * Q_bh [S,64] @ K_bh^T
// Q,K layout: [(b*S+s)*D + h*64 + k]. Grid (S/64, S/64, B*H), 256 thr,
// 64x64 output tile, 4x4 per thread, full K=64 in smem.
// ---------------------------------------------------------------------------
__global__ __launch_bounds__(256, 2)
void attn_scores(const float* __restrict__ Q, const float* __restrict__ K,
                 float* __restrict__ Sc, float scale)
{
    const int bh = blockIdx.z;
    const int b = bh >> 4;
    const int hd = bh & 15;
    const int row0 = blockIdx.y * 64;
    const int col0 = blockIdx.x * 64;
    const float* Qb = Q + (size_t)b * SS * DD + hd * 64;
    const float* Kb = K + (size_t)b * SS * DD + hd * 64;

    __shared__ float Qs[64][64]; // [k][row]
    __shared__ float Ks[64][64]; // [k][col]
    const int tid = threadIdx.x;
    const int lr = tid >> 4;          // 0..15
    const int lc4 = (tid & 15) << 2;  // 0..60
#pragma unroll
    for (int p = 0; p < 4; p++) {
        int r = lr + p * 16;
        float4 q = *(const float4*)(Qb + (size_t)(row0 + r) * DD + lc4);
        Qs[lc4 + 0][r] = q.x; Qs[lc4 + 1][r] = q.y;
        Qs[lc4 + 2][r] = q.z; Qs[lc4 + 3][r] = q.w;
        float4 k = *(const float4*)(Kb + (size_t)(col0 + r) * DD + lc4);
        Ks[lc4 + 0][r] = k.x; Ks[lc4 + 1][r] = k.y;
        Ks[lc4 + 2][r] = k.z; Ks[lc4 + 3][r] = k.w;
    }
    __syncthreads();

    const int tx = tid & 15, ty = tid >> 4;
    float acc[4][4];
#pragma unroll
    for (int i = 0; i < 4; i++)
#pragma unroll
        for (int j = 0; j < 4; j++) acc[i][j] = 0.f;

#pragma unroll
    for (int k = 0; k < 64; k++) {
        float4 a = *(const float4*)(&Qs[k][ty * 4]);
        float4 bv = *(const float4*)(&Ks[k][tx * 4]);
        float aa[4] = {a.x, a.y, a.z, a.w};
        float bb[4] = {bv.x, bv.y, bv.z, bv.w};
#pragma unroll
        for (int i = 0; i < 4; i++)
#pragma unroll
            for (int j = 0; j < 4; j++)
                acc[i][j] = fmaf(aa[i], bb[j], acc[i][j]);
    }

    float* Sb = Sc + (size_t)bh * SS * SS;
#pragma unroll
    for (int i = 0; i < 4; i++) {
        float4 v;
        v.x = acc[i][0] * scale; v.y = acc[i][1] * scale;
        v.z = acc[i][2] * scale; v.w = acc[i][3] * scale;
        *(float4*)(Sb + (size_t)(row0 + ty * 4 + i) * SS + col0 + tx * 4) = v;
    }
}

// ---------------------------------------------------------------------------
// Row softmax over 1024 elements. One block (256 thr) per row.
// NOTE: the per-head cosine "empathy bias" is constant along the softmax
// axis, so it cancels exactly — skipped by construction.
// ---------------------------------------------------------------------------
__global__ void softmax_rows(float* __restrict__ Sc)
{
    float* p = Sc + (size_t)blockIdx.x * SS;
    const int tid = threadIdx.x;
    __shared__ float red[8];

    float4 x = *(float4*)(p + tid * 4);
    float m = fmaxf(fmaxf(x.x, x.y), fmaxf(x.z, x.w));
#pragma unroll
    for (int o = 16; o; o >>= 1) m = fmaxf(m, __shfl_xor_sync(0xffffffffu, m, o));
    if ((tid & 31) == 0) red[tid >> 5] = m;
    __syncthreads();
    float bm = red[0];
#pragma unroll
    for (int i = 1; i < 8; i++) bm = fmaxf(bm, red[i]);
    __syncthreads();

    x.x = expf(x.x - bm); x.y = expf(x.y - bm);
    x.z = expf(x.z - bm); x.w = expf(x.w - bm);
    float s = x.x + x.y + x.z + x.w;
#pragma unroll
    for (int o = 16; o; o >>= 1) s += __shfl_xor_sync(0xffffffffu, s, o);
    if ((tid & 31) == 0) red[tid >> 5] = s;
    __syncthreads();
    float bs = 0.f;
#pragma unroll
    for (int i = 0; i < 8; i++) bs += red[i];
    float inv = 1.0f / bs;
    x.x *= inv; x.y *= inv; x.z *= inv; x.w *= inv;
    *(float4*)(p + tid * 4) = x;
}

// ---------------------------------------------------------------------------
// attn = P @ V per (b,h): M=S=1024, N=64, K=S=1024. Grid (S/64, 1, B*H),
// tile 64x64, BK=32, 4x4 per thread. Output layout [b,s, h*64+d].
// ---------------------------------------------------------------------------
__global__ __launch_bounds__(256, 2)
void attn_av(const float* __restrict__ P, const float* __restrict__ V,
             float* __restrict__ O)
{
    const int bh = blockIdx.z;
    const int b = bh >> 4;
    const int hd = bh & 15;
    const int row0 = blockIdx.x * 64;
    const float* Pb = P + (size_t)bh * SS * SS;
    const float* Vb = V + (size_t)b * SS * DD + hd * 64;
    float* Ob = O + (size_t)b * SS * DD + hd * 64;

    __shared__ float Ps[32][64]; // [k][row]
    __shared__ float Vs[32][64]; // [k][col]
    const int tid = threadIdx.x;
    const int lr = tid >> 3;          // 0..31
    const int lk4 = (tid & 7) << 2;   // 0..28
    const int vr = tid >> 4;          // 0..15
    const int vc4 = (tid & 15) << 2;  // 0..60
    const int tx = tid & 15, ty = tid >> 4;

    float acc[4][4];
#pragma unroll
    for (int i = 0; i < 4; i++)
#pragma unroll
        for (int j = 0; j < 4; j++) acc[i][j] = 0.f;

    for (int kk = 0; kk < SS; kk += 32) {
#pragma unroll
        for (int ph = 0; ph < 2; ph++) {
            int r = lr + ph * 32;
            float4 pv = *(const float4*)(Pb + (size_t)(row0 + r) * SS + kk + lk4);
            Ps[lk4 + 0][r] = pv.x; Ps[lk4 + 1][r] = pv.y;
            Ps[lk4 + 2][r] = pv.z; Ps[lk4 + 3][r] = pv.w;
        }
#pragma unroll
        for (int ph = 0; ph < 2; ph++) {
            int r = vr + ph * 16;
            float4 vv = *(const float4*)(Vb + (size_t)(kk + r) * DD + vc4);
            *(float4*)(&Vs[r][vc4]) = vv;
        }
        __syncthreads();
#pragma unroll
        for (int k = 0; k < 32; k++) {
            float4 a = *(const float4*)(&Ps[k][ty * 4]);
            float4 bv = *(const float4*)(&Vs[k][tx * 4]);
            float aa[4] = {a.x, a.y, a.z, a.w};
            float bb[4] = {bv.x, bv.y, bv.z, bv.w};
#pragma unroll
            for (int i = 0; i < 4; i++)
#pragma unroll
                for (int j = 0; j < 4; j++)
                    acc[i][j] = fmaf(aa[i], bb[j], acc[i][j]);
        }
        __syncthreads();
    }

#pragma unroll
    for (int i = 0; i < 4; i++) {
        float4 v = {acc[i][0], acc[i][1], acc[i][2], acc[i][3]};
        *(float4*)(Ob + (size_t)(row0 + ty * 4 + i) * DD + tx * 4) = v;
    }
}

// ---------------------------------------------------------------------------
// Fused residual + LayerNorm: h = LN(h + y) * g + be. One block per token row.
// ---------------------------------------------------------------------------
__global__ void add_ln(float* __restrict__ h, const float* __restrict__ y,
                       const float* __restrict__ g, const float* __restrict__ be)
{
    float* hr = h + (size_t)blockIdx.x * DD;
    const float* yr = y + (size_t)blockIdx.x * DD;
    const int tid = threadIdx.x;
    __shared__ float red[8];

    float4 hv = *(float4*)(hr + tid * 4);
    float4 yv = *(const float4*)(yr + tid * 4);
    float z[4] = {hv.x + yv.x, hv.y + yv.y, hv.z + yv.z, hv.w + yv.w};

    float s = z[0] + z[1] + z[2] + z[3];
#pragma unroll
    for (int o = 16; o; o >>= 1) s += __shfl_xor_sync(0xffffffffu, s, o);
    if ((tid & 31) == 0) red[tid >> 5] = s;
    __syncthreads();
    float tot = 0.f;
#pragma unroll
    for (int i = 0; i < 8; i++) tot += red[i];
    float mean = tot * (1.0f / DD);
    __syncthreads();

    float d0 = z[0] - mean, d1 = z[1] - mean, d2 = z[2] - mean, d3 = z[3] - mean;
    float vs = d0 * d0 + d1 * d1 + d2 * d2 + d3 * d3;
#pragma unroll
    for (int o = 16; o; o >>= 1) vs += __shfl_xor_sync(0xffffffffu, vs, o);
    if ((tid & 31) == 0) red[tid >> 5] = vs;
    __syncthreads();
    float vtot = 0.f;
#pragma unroll
    for (int i = 0; i < 8; i++) vtot += red[i];
    float rstd = rsqrtf(vtot * (1.0f / DD) + 1e-5f);

    float4 gv = *(const float4*)(g + tid * 4);
    float4 bv = *(const float4*)(be + tid * 4);
    float4 o;
    o.x = d0 * rstd * gv.x + bv.x;
    o.y = d1 * rstd * gv.y + bv.y;
    o.z = d2 * rstd * gv.z + bv.z;
    o.w = d3 * rstd * gv.w + bv.w;
    *(float4*)(hr + tid * 4) = o;
}

// ---------------------------------------------------------------------------
// Launch
// ---------------------------------------------------------------------------
extern "C" void kernel_launch(void* const* d_in, const int* in_sizes, int n_in,
                              void* d_out, int out_size)
{
    const int*   x     = (const int*)d_in[0];
    const float* noise = (const float*)d_in[1];
    const float* emb   = (const float*)d_in[2];
    const float* Wq    = (const float*)d_in[3];
    const float* bq    = (const float*)d_in[4];
    const float* Wk    = (const float*)d_in[5];
    const float* bk    = (const float*)d_in[6];
    const float* Wv    = (const float*)d_in[7];
    const float* bv    = (const float*)d_in[8];
    const float* Wo    = (const float*)d_in[9];
    const float* bo    = (const float*)d_in[10];
    const float* W1f   = (const float*)d_in[11];
    const float* b1f   = (const float*)d_in[12];
    const float* W2f   = (const float*)d_in[13];
    const float* b2f   = (const float*)d_in[14];
    const float* g1    = (const float*)d_in[15];
    const float* be1   = (const float*)d_in[16];
    const float* g2    = (const float*)d_in[17];
    const float* be2   = (const float*)d_in[18];
    const float* Wout  = (const float*)d_in[19];
    const float* bout  = (const float*)d_in[20];
    float* out = (float*)d_out;

    float *h, *q, *k, *v, *attn, *t1, *t2, *sc;
    cudaGetSymbolAddress((void**)&h, g_h);
    cudaGetSymbolAddress((void**)&q, g_q);
    cudaGetSymbolAddress((void**)&k, g_k);
    cudaGetSymbolAddress((void**)&v, g_v);
    cudaGetSymbolAddress((void**)&attn, g_attn);
    cudaGetSymbolAddress((void**)&t1, g_t1);
    cudaGetSymbolAddress((void**)&t2, g_t2);
    cudaGetSymbolAddress((void**)&sc, g_scores);

    embed_kernel<<<(MTOK * DD) / 256, 256>>>(x, noise, emb, h);

    const float scale = 0.125f; // 1/sqrt(64)

    for (int i = 0; i < LL; i++) {
        const float* Wq_i = Wq + (size_t)i * DD * DD;
        const float* Wk_i = Wk + (size_t)i * DD * DD;
        const float* Wv_i = Wv + (size_t)i * DD * DD;
        const float* Wo_i = Wo + (size_t)i * DD * DD;
        const float* W1_i = W1f + (size_t)i * DD * FFF;
        const float* W2_i = W2f + (size_t)i * FFF * DD;

        sgemm128<<<dim3(DD / 128, MTOK / 128), 256>>>(h, Wq_i, bq + i * DD, q, MTOK, DD, DD, 0);
        sgemm128<<<dim3(DD / 128, MTOK / 128), 256>>>(h, Wk_i, bk + i * DD, k, MTOK, DD, DD, 0);
        sgemm128<<<dim3(DD / 128, MTOK / 128), 256>>>(h, Wv_i, bv + i * DD, v, MTOK, DD, DD, 0);

        attn_scores<<<dim3(SS / 64, SS / 64, BB * HH), 256>>>(q, k, sc, scale);
        softmax_rows<<<BB * HH * SS, 256>>>(sc);
        attn_av<<<dim3(SS / 64, 1, BB * HH), 256>>>(sc, v, attn);

        sgemm128<<<dim3(DD / 128, MTOK / 128), 256>>>(attn, Wo_i, bo + i * DD, t2, MTOK, DD, DD, 0);
        add_ln<<<MTOK, 256>>>(h, t2, g1 + i * DD, be1 + i * DD);

        sgemm128<<<dim3(FFF / 128, MTOK / 128), 256>>>(h, W1_i, b1f + i * FFF, t1, MTOK, FFF, DD, 1);
        sgemm128<<<dim3(DD / 128, MTOK / 128), 256>>>(t1, W2_i, b2f + i * DD, t2, MTOK, DD, FFF, 0);
        add_ln<<<MTOK, 256>>>(h, t2, g2 + i * DD, be2 + i * DD);
    }

    sgemm128<<<dim3(VV / 128, MTOK / 128), 256>>>(h, Wout, bout, out, MTOK, VV, DD, 0);
}

// round 2
// speedup vs baseline: 1.5892x; 1.5892x over previous
#include <cuda_runtime.h>
#include <cuda_bf16.h>
#include <math.h>
#include <stdint.h>

// Problem constants
#define BB 2
#define SS 1024
#define DD 1024
#define HH 16
#define LL 3
#define FFF 4096
#define VV 32000
#define MTOK (BB*SS)   // 2048 tokens

// ---------------------------------------------------------------------------
// Scratch (allocation-free: __device__ globals)
// ---------------------------------------------------------------------------
__device__ float g_h[MTOK * DD];
__device__ float g_q[MTOK * DD];
__device__ float g_k[MTOK * DD];
__device__ float g_v[MTOK * DD];
__device__ float g_attn[MTOK * DD];
__device__ float g_t2[MTOK * DD];
__device__ float g_t1[MTOK * FFF];
__device__ float g_scores[(size_t)BB * HH * SS * SS];

// ---------------------------------------------------------------------------
// Embedding: h = emb[x] + 0.05 * noise
// ---------------------------------------------------------------------------
__global__ void embed_kernel(const int* __restrict__ x,
                             const float* __restrict__ noise,
                             const float* __restrict__ emb,
                             float* __restrict__ h)
{
    size_t idx = (size_t)blockIdx.x * blockDim.x + threadIdx.x;
    size_t tok = idx >> 10;
    int d = (int)(idx & 1023);
    h[idx] = emb[(size_t)x[tok] * DD + d] + noise[idx] * 0.05f;
}

// ---------------------------------------------------------------------------
// Split-bf16 tensor-core GEMM: C[M,N] = A[M,K] @ B[K,N] + bias, opt ReLU.
// fp32 emulated as hi+lo bf16; D = Ah*Bh + Ah*Bl + Al*Bh (error ~2^-17).
// Block tile 128x128, K-step 16, 256 threads (8 warps, 2x4), warp tile 64x32,
// mma.sync.m16n8k16. Requires M%128==0, N%128==0, K%16==0.
// ---------------------------------------------------------------------------
#define MMA_BF16(c, a, b)                                                     \
    asm volatile("mma.sync.aligned.m16n8k16.row.col.f32.bf16.bf16.f32 "       \
                 "{%0,%1,%2,%3}, {%4,%5,%6,%7}, {%8,%9}, {%0,%1,%2,%3};"      \
                 : "+f"(c[0]), "+f"(c[1]), "+f"(c[2]), "+f"(c[3])             \
                 : "r"(a[0]), "r"(a[1]), "r"(a[2]), "r"(a[3]),                \
                   "r"(b[0]), "r"(b[1]))

__device__ __forceinline__ uint32_t pack_hi2(float x, float y) {
    __nv_bfloat162 v = __halves2bfloat162(__float2bfloat16_rn(x),
                                          __float2bfloat16_rn(y));
    return *reinterpret_cast<uint32_t*>(&v);
}
__device__ __forceinline__ uint32_t pack_lo2(float x, float y) {
    float rx = x - __bfloat162float(__float2bfloat16_rn(x));
    float ry = y - __bfloat162float(__float2bfloat16_rn(y));
    __nv_bfloat162 v = __halves2bfloat162(__float2bfloat16_rn(rx),
                                          __float2bfloat16_rn(ry));
    return *reinterpret_cast<uint32_t*>(&v);
}

__global__ __launch_bounds__(256)
void bgemm128(const float* __restrict__ A, const float* __restrict__ B,
              const float* __restrict__ bias, float* __restrict__ C,
              int M, int N, int K, int relu)
{
    __shared__ __nv_bfloat16 As_h[128][18];
    __shared__ __nv_bfloat16 As_l[128][18];
    __shared__ __nv_bfloat16 Bs_h[128][18];
    __shared__ __nv_bfloat16 Bs_l[128][18];

    const int tid = threadIdx.x;
    const int bm = blockIdx.y * 128;
    const int bn = blockIdx.x * 128;

    const int lane = tid & 31;
    const int wid  = tid >> 5;
    const int grp  = lane >> 2;        // 0..7
    const int kp   = (lane & 3) << 1;  // 0,2,4,6
    const int wm   = (wid & 1) * 64;
    const int wn   = (wid >> 1) * 32;

    // gmem load mapping
    const int a_r  = tid >> 2;            // 0..63 (rows, +64 second pass)
    const int a_c  = (tid & 3) << 2;      // k within tile: 0,4,8,12
    const int b_r  = tid >> 5;            // 0..7 (k rows, +8 second pass)
    const int b_c  = (tid & 31) << 2;     // n within tile: 0..124

    float acc[4][4][4];
#pragma unroll
    for (int i = 0; i < 4; i++)
#pragma unroll
        for (int j = 0; j < 4; j++)
#pragma unroll
            for (int e = 0; e < 4; e++) acc[i][j][e] = 0.f;

    // prefetch tile 0
    float4 ra[2], rb[2];
#pragma unroll
    for (int p = 0; p < 2; p++) {
        ra[p] = *(const float4*)(A + (size_t)(bm + a_r + p * 64) * K + a_c);
        rb[p] = *(const float4*)(B + (size_t)(b_r + p * 8) * N + bn + b_c);
    }

    for (int k0 = 0; k0 < K; k0 += 16) {
        // store current tile (convert fp32 -> hi/lo bf16)
#pragma unroll
        for (int p = 0; p < 2; p++) {
            int r = a_r + p * 64;
            *(uint32_t*)&As_h[r][a_c]     = pack_hi2(ra[p].x, ra[p].y);
            *(uint32_t*)&As_h[r][a_c + 2] = pack_hi2(ra[p].z, ra[p].w);
            *(uint32_t*)&As_l[r][a_c]     = pack_lo2(ra[p].x, ra[p].y);
            *(uint32_t*)&As_l[r][a_c + 2] = pack_lo2(ra[p].z, ra[p].w);
        }
#pragma unroll
        for (int p = 0; p < 2; p++) {
            int kr = b_r + p * 8;
            float v[4] = {rb[p].x, rb[p].y, rb[p].z, rb[p].w};
#pragma unroll
            for (int e = 0; e < 4; e++) {
                int n = b_c + e;
                __nv_bfloat16 hb = __float2bfloat16_rn(v[e]);
                Bs_h[n][kr] = hb;
                Bs_l[n][kr] = __float2bfloat16_rn(v[e] - __bfloat162float(hb));
            }
        }
        __syncthreads();

        // prefetch next tile
        if (k0 + 16 < K) {
#pragma unroll
            for (int p = 0; p < 2; p++) {
                ra[p] = *(const float4*)(A + (size_t)(bm + a_r + p * 64) * K + k0 + 16 + a_c);
                rb[p] = *(const float4*)(B + (size_t)(k0 + 16 + b_r + p * 8) * N + bn + b_c);
            }
        }

        // fragments
        uint32_t Ah[4][4], Al[4][4], Bh[4][2], Bl[4][2];
#pragma unroll
        for (int i = 0; i < 4; i++) {
            int m0 = wm + i * 16 + grp;
            Ah[i][0] = *(uint32_t*)&As_h[m0][kp];
            Ah[i][1] = *(uint32_t*)&As_h[m0 + 8][kp];
            Ah[i][2] = *(uint32_t*)&As_h[m0][kp + 8];
            Ah[i][3] = *(uint32_t*)&As_h[m0 + 8][kp + 8];
            Al[i][0] = *(uint32_t*)&As_l[m0][kp];
            Al[i][1] = *(uint32_t*)&As_l[m0 + 8][kp];
            Al[i][2] = *(uint32_t*)&As_l[m0][kp + 8];
            Al[i][3] = *(uint32_t*)&As_l[m0 + 8][kp + 8];
        }
#pragma unroll
        for (int j = 0; j < 4; j++) {
            int n0 = wn + j * 8 + grp;
            Bh[j][0] = *(uint32_t*)&Bs_h[n0][kp];
            Bh[j][1] = *(uint32_t*)&Bs_h[n0][kp + 8];
            Bl[j][0] = *(uint32_t*)&Bs_l[n0][kp];
            Bl[j][1] = *(uint32_t*)&Bs_l[n0][kp + 8];
        }

#pragma unroll
        for (int i = 0; i < 4; i++)
#pragma unroll
            for (int j = 0; j < 4; j++) {
                MMA_BF16(acc[i][j], Ah[i], Bh[j]);
                MMA_BF16(acc[i][j], Ah[i], Bl[j]);
                MMA_BF16(acc[i][j], Al[i], Bh[j]);
            }
        __syncthreads();
    }

    // epilogue
#pragma unroll
    for (int i = 0; i < 4; i++) {
        int row0 = bm + wm + i * 16 + grp;
#pragma unroll
        for (int j = 0; j < 4; j++) {
            int col0 = bn + wn + j * 8 + kp;
            float bx = bias[col0], by = bias[col0 + 1];
            float2 v0, v1;
            v0.x = acc[i][j][0] + bx; v0.y = acc[i][j][1] + by;
            v1.x = acc[i][j][2] + bx; v1.y = acc[i][j][3] + by;
            if (relu) {
                v0.x = fmaxf(v0.x, 0.f); v0.y = fmaxf(v0.y, 0.f);
                v1.x = fmaxf(v1.x, 0.f); v1.y = fmaxf(v1.y, 0.f);
            }
            *(float2*)(C + (size_t)row0 * N + col0) = v0;
            *(float2*)(C + (size_t)(row0 + 8) * N + col0) = v1;
        }
    }
}

// ---------------------------------------------------------------------------
// Attention scores (fp32): per (b,h): S = scale * Q_bh [S,64] @ K_bh^T
// ---------------------------------------------------------------------------
__global__ __launch_bounds__(256, 2)
void attn_scores(const float* __restrict__ Q, const float* __restrict__ K,
                 float* __restrict__ Sc, float scale)
{
    const int bh = blockIdx.z;
    const int b = bh >> 4;
    const int hd = bh & 15;
    const int row0 = blockIdx.y * 64;
    const int col0 = blockIdx.x * 64;
    const float* Qb = Q + (size_t)b * SS * DD + hd * 64;
    const float* Kb = K + (size_t)b * SS * DD + hd * 64;

    __shared__ float Qs[64][64];
    __shared__ float Ks[64][64];
    const int tid = threadIdx.x;
    const int lr = tid >> 4;
    const int lc4 = (tid & 15) << 2;
#pragma unroll
    for (int p = 0; p < 4; p++) {
        int r = lr + p * 16;
        float4 q = *(const float4*)(Qb + (size_t)(row0 + r) * DD + lc4);
        Qs[lc4 + 0][r] = q.x; Qs[lc4 + 1][r] = q.y;
        Qs[lc4 + 2][r] = q.z; Qs[lc4 + 3][r] = q.w;
        float4 k = *(const float4*)(Kb + (size_t)(col0 + r) * DD + lc4);
        Ks[lc4 + 0][r] = k.x; Ks[lc4 + 1][r] = k.y;
        Ks[lc4 + 2][r] = k.z; Ks[lc4 + 3][r] = k.w;
    }
    __syncthreads();

    const int tx = tid & 15, ty = tid >> 4;
    float acc[4][4];
#pragma unroll
    for (int i = 0; i < 4; i++)
#pragma unroll
        for (int j = 0; j < 4; j++) acc[i][j] = 0.f;

#pragma unroll
    for (int k = 0; k < 64; k++) {
        float4 a = *(const float4*)(&Qs[k][ty * 4]);
        float4 bv = *(const float4*)(&Ks[k][tx * 4]);
        float aa[4] = {a.x, a.y, a.z, a.w};
        float bb[4] = {bv.x, bv.y, bv.z, bv.w};
#pragma unroll
        for (int i = 0; i < 4; i++)
#pragma unroll
            for (int j = 0; j < 4; j++)
                acc[i][j] = fmaf(aa[i], bb[j], acc[i][j]);
    }

    float* Sb = Sc + (size_t)bh * SS * SS;
#pragma unroll
    for (int i = 0; i < 4; i++) {
        float4 v;
        v.x = acc[i][0] * scale; v.y = acc[i][1] * scale;
        v.z = acc[i][2] * scale; v.w = acc[i][3] * scale;
        *(float4*)(Sb + (size_t)(row0 + ty * 4 + i) * SS + col0 + tx * 4) = v;
    }
}

// ---------------------------------------------------------------------------
// Row softmax (empathy bias is row-constant -> cancels; skipped).
// ---------------------------------------------------------------------------
__global__ void softmax_rows(float* __restrict__ Sc)
{
    float* p = Sc + (size_t)blockIdx.x * SS;
    const int tid = threadIdx.x;
    __shared__ float red[8];

    float4 x = *(float4*)(p + tid * 4);
    float m = fmaxf(fmaxf(x.x, x.y), fmaxf(x.z, x.w));
#pragma unroll
    for (int o = 16; o; o >>= 1) m = fmaxf(m, __shfl_xor_sync(0xffffffffu, m, o));
    if ((tid & 31) == 0) red[tid >> 5] = m;
    __syncthreads();
    float bm = red[0];
#pragma unroll
    for (int i = 1; i < 8; i++) bm = fmaxf(bm, red[i]);
    __syncthreads();

    x.x = expf(x.x - bm); x.y = expf(x.y - bm);
    x.z = expf(x.z - bm); x.w = expf(x.w - bm);
    float s = x.x + x.y + x.z + x.w;
#pragma unroll
    for (int o = 16; o; o >>= 1) s += __shfl_xor_sync(0xffffffffu, s, o);
    if ((tid & 31) == 0) red[tid >> 5] = s;
    __syncthreads();
    float bs = 0.f;
#pragma unroll
    for (int i = 0; i < 8; i++) bs += red[i];
    float inv = 1.0f / bs;
    x.x *= inv; x.y *= inv; x.z *= inv; x.w *= inv;
    *(float4*)(p + tid * 4) = x;
}

// ---------------------------------------------------------------------------
// attn = P @ V per (b,h) (fp32)
// ---------------------------------------------------------------------------
__global__ __launch_bounds__(256, 2)
void attn_av(const float* __restrict__ P, const float* __restrict__ V,
             float* __restrict__ O)
{
    const int bh = blockIdx.z;
    const int b = bh >> 4;
    const int hd = bh & 15;
    const int row0 = blockIdx.x * 64;
    const float* Pb = P + (size_t)bh * SS * SS;
    const float* Vb = V + (size_t)b * SS * DD + hd * 64;
    float* Ob = O + (size_t)b * SS * DD + hd * 64;

    __shared__ float Ps[32][64];
    __shared__ float Vs[32][64];
    const int tid = threadIdx.x;
    const int lr = tid >> 3;
    const int lk4 = (tid & 7) << 2;
    const int vr = tid >> 4;
    const int vc4 = (tid & 15) << 2;
    const int tx = tid & 15, ty = tid >> 4;

    float acc[4][4];
#pragma unroll
    for (int i = 0; i < 4; i++)
#pragma unroll
        for (int j = 0; j < 4; j++) acc[i][j] = 0.f;

    for (int kk = 0; kk < SS; kk += 32) {
#pragma unroll
        for (int ph = 0; ph < 2; ph++) {
            int r = lr + ph * 32;
            float4 pv = *(const float4*)(Pb + (size_t)(row0 + r) * SS + kk + lk4);
            Ps[lk4 + 0][r] = pv.x; Ps[lk4 + 1][r] = pv.y;
            Ps[lk4 + 2][r] = pv.z; Ps[lk4 + 3][r] = pv.w;
        }
#pragma unroll
        for (int ph = 0; ph < 2; ph++) {
            int r = vr + ph * 16;
            float4 vv = *(const float4*)(Vb + (size_t)(kk + r) * DD + vc4);
            *(float4*)(&Vs[r][vc4]) = vv;
        }
        __syncthreads();
#pragma unroll
        for (int k = 0; k < 32; k++) {
            float4 a = *(const float4*)(&Ps[k][ty * 4]);
            float4 bv = *(const float4*)(&Vs[k][tx * 4]);
            float aa[4] = {a.x, a.y, a.z, a.w};
            float bb[4] = {bv.x, bv.y, bv.z, bv.w};
#pragma unroll
            for (int i = 0; i < 4; i++)
#pragma unroll
                for (int j = 0; j < 4; j++)
                    acc[i][j] = fmaf(aa[i], bb[j], acc[i][j]);
        }
        __syncthreads();
    }

#pragma unroll
    for (int i = 0; i < 4; i++) {
        float4 v = {acc[i][0], acc[i][1], acc[i][2], acc[i][3]};
        *(float4*)(Ob + (size_t)(row0 + ty * 4 + i) * DD + tx * 4) = v;
    }
}

// ---------------------------------------------------------------------------
// Fused residual + LayerNorm
// ---------------------------------------------------------------------------
__global__ void add_ln(float* __restrict__ h, const float* __restrict__ y,
                       const float* __restrict__ g, const float* __restrict__ be)
{
    float* hr = h + (size_t)blockIdx.x * DD;
    const float* yr = y + (size_t)blockIdx.x * DD;
    const int tid = threadIdx.x;
    __shared__ float red[8];

    float4 hv = *(float4*)(hr + tid * 4);
    float4 yv = *(const float4*)(yr + tid * 4);
    float z[4] = {hv.x + yv.x, hv.y + yv.y, hv.z + yv.z, hv.w + yv.w};

    float s = z[0] + z[1] + z[2] + z[3];
#pragma unroll
    for (int o = 16; o; o >>= 1) s += __shfl_xor_sync(0xffffffffu, s, o);
    if ((tid & 31) == 0) red[tid >> 5] = s;
    __syncthreads();
    float tot = 0.f;
#pragma unroll
    for (int i = 0; i < 8; i++) tot += red[i];
    float mean = tot * (1.0f / DD);
    __syncthreads();

    float d0 = z[0] - mean, d1 = z[1] - mean, d2 = z[2] - mean, d3 = z[3] - mean;
    float vs = d0 * d0 + d1 * d1 + d2 * d2 + d3 * d3;
#pragma unroll
    for (int o = 16; o; o >>= 1) vs += __shfl_xor_sync(0xffffffffu, vs, o);
    if ((tid & 31) == 0) red[tid >> 5] = vs;
    __syncthreads();
    float vtot = 0.f;
#pragma unroll
    for (int i = 0; i < 8; i++) vtot += red[i];
    float rstd = rsqrtf(vtot * (1.0f / DD) + 1e-5f);

    float4 gv = *(const float4*)(g + tid * 4);
    float4 bv = *(const float4*)(be + tid * 4);
    float4 o;
    o.x = d0 * rstd * gv.x + bv.x;
    o.y = d1 * rstd * gv.y + bv.y;
    o.z = d2 * rstd * gv.z + bv.z;
    o.w = d3 * rstd * gv.w + bv.w;
    *(float4*)(hr + tid * 4) = o;
}

// ---------------------------------------------------------------------------
// Launch
// ---------------------------------------------------------------------------
extern "C" void kernel_launch(void* const* d_in, const int* in_sizes, int n_in,
                              void* d_out, int out_size)
{
    const int*   x     = (const int*)d_in[0];
    const float* noise = (const float*)d_in[1];
    const float* emb   = (const float*)d_in[2];
    const float* Wq    = (const float*)d_in[3];
    const float* bq    = (const float*)d_in[4];
    const float* Wk    = (const float*)d_in[5];
    const float* bk    = (const float*)d_in[6];
    const float* Wv    = (const float*)d_in[7];
    const float* bv    = (const float*)d_in[8];
    const float* Wo    = (const float*)d_in[9];
    const float* bo    = (const float*)d_in[10];
    const float* W1f   = (const float*)d_in[11];
    const float* b1f   = (const float*)d_in[12];
    const float* W2f   = (const float*)d_in[13];
    const float* b2f   = (const float*)d_in[14];
    const float* g1    = (const float*)d_in[15];
    const float* be1   = (const float*)d_in[16];
    const float* g2    = (const float*)d_in[17];
    const float* be2   = (const float*)d_in[18];
    const float* Wout  = (const float*)d_in[19];
    const float* bout  = (const float*)d_in[20];
    float* out = (float*)d_out;

    float *h, *q, *k, *v, *attn, *t1, *t2, *sc;
    cudaGetSymbolAddress((void**)&h, g_h);
    cudaGetSymbolAddress((void**)&q, g_q);
    cudaGetSymbolAddress((void**)&k, g_k);
    cudaGetSymbolAddress((void**)&v, g_v);
    cudaGetSymbolAddress((void**)&attn, g_attn);
    cudaGetSymbolAddress((void**)&t1, g_t1);
    cudaGetSymbolAddress((void**)&t2, g_t2);
    cudaGetSymbolAddress((void**)&sc, g_scores);

    embed_kernel<<<(MTOK * DD) / 256, 256>>>(x, noise, emb, h);

    const float scale = 0.125f; // 1/sqrt(64)

    for (int i = 0; i < LL; i++) {
        const float* Wq_i = Wq + (size_t)i * DD * DD;
        const float* Wk_i = Wk + (size_t)i * DD * DD;
        const float* Wv_i = Wv + (size_t)i * DD * DD;
        const float* Wo_i = Wo + (size_t)i * DD * DD;
        const float* W1_i = W1f + (size_t)i * DD * FFF;
        const float* W2_i = W2f + (size_t)i * FFF * DD;

        bgemm128<<<dim3(DD / 128, MTOK / 128), 256>>>(h, Wq_i, bq + i * DD, q, MTOK, DD, DD, 0);
        bgemm128<<<dim3(DD / 128, MTOK / 128), 256>>>(h, Wk_i, bk + i * DD, k, MTOK, DD, DD, 0);
        bgemm128<<<dim3(DD / 128, MTOK / 128), 256>>>(h, Wv_i, bv + i * DD, v, MTOK, DD, DD, 0);

        attn_scores<<<dim3(SS / 64, SS / 64, BB * HH), 256>>>(q, k, sc, scale);
        softmax_rows<<<BB * HH * SS, 256>>>(sc);
        attn_av<<<dim3(SS / 64, 1, BB * HH), 256>>>(sc, v, attn);

        bgemm128<<<dim3(DD / 128, MTOK / 128), 256>>>(attn, Wo_i, bo + i * DD, t2, MTOK, DD, DD, 0);
        add_ln<<<MTOK, 256>>>(h, t2, g1 + i * DD, be1 + i * DD);

        bgemm128<<<dim3(FFF / 128, MTOK / 128), 256>>>(h, W1_i, b1f + i * FFF, t1, MTOK, FFF, DD, 1);
        bgemm128<<<dim3(DD / 128, MTOK / 128), 256>>>(t1, W2_i, b2f + i * DD, t2, MTOK, DD, FFF, 0);
        add_ln<<<MTOK, 256>>>(h, t2, g2 + i * DD, be2 + i * DD);
    }

    bgemm128<<<dim3(VV / 128, MTOK / 128), 256>>>(h, Wout, bout, out, MTOK, VV, DD, 0);
}

// round 3
// speedup vs baseline: 1.5895x; 1.0002x over previous
#include <cuda_runtime.h>
#include <cuda_bf16.h>
#include <math.h>
#include <stdint.h>

// Problem constants
#define BB 2
#define SS 1024
#define DD 1024
#define HH 16
#define LL 3
#define FFF 4096
#define VV 32000
#define MTOK (BB*SS)   // 2048 tokens

// ---------------------------------------------------------------------------
// Scratch (allocation-free: __device__ globals)
// ---------------------------------------------------------------------------
__device__ float g_h[MTOK * DD];
__device__ float g_q[MTOK * DD];
__device__ float g_k[MTOK * DD];
__device__ float g_v[MTOK * DD];
__device__ float g_attn[MTOK * DD];
__device__ float g_t2[MTOK * DD];
__device__ float g_t1[MTOK * FFF];
__device__ float g_scores[(size_t)BB * HH * SS * SS];

// ---------------------------------------------------------------------------
// Embedding: h = emb[x] + 0.05 * noise
// ---------------------------------------------------------------------------
__global__ void embed_kernel(const int* __restrict__ x,
                             const float* __restrict__ noise,
                             const float* __restrict__ emb,
                             float* __restrict__ h)
{
    size_t idx = (size_t)blockIdx.x * blockDim.x + threadIdx.x;
    size_t tok = idx >> 10;
    int d = (int)(idx & 1023);
    h[idx] = emb[(size_t)x[tok] * DD + d] + noise[idx] * 0.05f;
}

// ---------------------------------------------------------------------------
// Split-bf16 tensor-core GEMM: C[M,N] = A[M,K] @ B[K,N] + bias, opt ReLU.
// fp32 emulated as hi+lo bf16; D = Ah*Bh + Ah*Bl + Al*Bh (error ~2^-17).
// Block tile 128x128, K-step 16, 256 threads (8 warps, 2x4), warp tile 64x32,
// mma.sync.m16n8k16. Requires M%128==0, N%128==0, K%16==0.
// ---------------------------------------------------------------------------
#define MMA_BF16(c, a, b)                                                     \
    asm volatile("mma.sync.aligned.m16n8k16.row.col.f32.bf16.bf16.f32 "       \
                 "{%0,%1,%2,%3}, {%4,%5,%6,%7}, {%8,%9}, {%0,%1,%2,%3};"      \
                 : "+f"(c[0]), "+f"(c[1]), "+f"(c[2]), "+f"(c[3])             \
                 : "r"(a[0]), "r"(a[1]), "r"(a[2]), "r"(a[3]),                \
                   "r"(b[0]), "r"(b[1]))

__device__ __forceinline__ uint32_t pack_hi2(float x, float y) {
    __nv_bfloat162 v = __halves2bfloat162(__float2bfloat16_rn(x),
                                          __float2bfloat16_rn(y));
    return *reinterpret_cast<uint32_t*>(&v);
}
__device__ __forceinline__ uint32_t pack_lo2(float x, float y) {
    float rx = x - __bfloat162float(__float2bfloat16_rn(x));
    float ry = y - __bfloat162float(__float2bfloat16_rn(y));
    __nv_bfloat162 v = __halves2bfloat162(__float2bfloat16_rn(rx),
                                          __float2bfloat16_rn(ry));
    return *reinterpret_cast<uint32_t*>(&v);
}

__global__ __launch_bounds__(256)
void bgemm128(const float* __restrict__ A, const float* __restrict__ B,
              const float* __restrict__ bias, float* __restrict__ C,
              int M, int N, int K, int relu)
{
    __shared__ __nv_bfloat16 As_h[128][18];
    __shared__ __nv_bfloat16 As_l[128][18];
    __shared__ __nv_bfloat16 Bs_h[128][18];
    __shared__ __nv_bfloat16 Bs_l[128][18];

    const int tid = threadIdx.x;
    const int bm = blockIdx.y * 128;
    const int bn = blockIdx.x * 128;

    const int lane = tid & 31;
    const int wid  = tid >> 5;
    const int grp  = lane >> 2;        // 0..7
    const int kp   = (lane & 3) << 1;  // 0,2,4,6
    const int wm   = (wid & 1) * 64;
    const int wn   = (wid >> 1) * 32;

    // gmem load mapping
    const int a_r  = tid >> 2;            // 0..63 (rows, +64 second pass)
    const int a_c  = (tid & 3) << 2;      // k within tile: 0,4,8,12
    const int b_r  = tid >> 5;            // 0..7 (k rows, +8 second pass)
    const int b_c  = (tid & 31) << 2;     // n within tile: 0..124

    float acc[4][4][4];
#pragma unroll
    for (int i = 0; i < 4; i++)
#pragma unroll
        for (int j = 0; j < 4; j++)
#pragma unroll
            for (int e = 0; e < 4; e++) acc[i][j][e] = 0.f;

    // prefetch tile 0
    float4 ra[2], rb[2];
#pragma unroll
    for (int p = 0; p < 2; p++) {
        ra[p] = *(const float4*)(A + (size_t)(bm + a_r + p * 64) * K + a_c);
        rb[p] = *(const float4*)(B + (size_t)(b_r + p * 8) * N + bn + b_c);
    }

    for (int k0 = 0; k0 < K; k0 += 16) {
        // store current tile (convert fp32 -> hi/lo bf16)
#pragma unroll
        for (int p = 0; p < 2; p++) {
            int r = a_r + p * 64;
            *(uint32_t*)&As_h[r][a_c]     = pack_hi2(ra[p].x, ra[p].y);
            *(uint32_t*)&As_h[r][a_c + 2] = pack_hi2(ra[p].z, ra[p].w);
            *(uint32_t*)&As_l[r][a_c]     = pack_lo2(ra[p].x, ra[p].y);
            *(uint32_t*)&As_l[r][a_c + 2] = pack_lo2(ra[p].z, ra[p].w);
        }
#pragma unroll
        for (int p = 0; p < 2; p++) {
            int kr = b_r + p * 8;
            float v[4] = {rb[p].x, rb[p].y, rb[p].z, rb[p].w};
#pragma unroll
            for (int e = 0; e < 4; e++) {
                int n = b_c + e;
                __nv_bfloat16 hb = __float2bfloat16_rn(v[e]);
                Bs_h[n][kr] = hb;
                Bs_l[n][kr] = __float2bfloat16_rn(v[e] - __bfloat162float(hb));
            }
        }
        __syncthreads();

        // prefetch next tile
        if (k0 + 16 < K) {
#pragma unroll
            for (int p = 0; p < 2; p++) {
                ra[p] = *(const float4*)(A + (size_t)(bm + a_r + p * 64) * K + k0 + 16 + a_c);
                rb[p] = *(const float4*)(B + (size_t)(k0 + 16 + b_r + p * 8) * N + bn + b_c);
            }
        }

        // fragments
        uint32_t Ah[4][4], Al[4][4], Bh[4][2], Bl[4][2];
#pragma unroll
        for (int i = 0; i < 4; i++) {
            int m0 = wm + i * 16 + grp;
            Ah[i][0] = *(uint32_t*)&As_h[m0][kp];
            Ah[i][1] = *(uint32_t*)&As_h[m0 + 8][kp];
            Ah[i][2] = *(uint32_t*)&As_h[m0][kp + 8];
            Ah[i][3] = *(uint32_t*)&As_h[m0 + 8][kp + 8];
            Al[i][0] = *(uint32_t*)&As_l[m0][kp];
            Al[i][1] = *(uint32_t*)&As_l[m0 + 8][kp];
            Al[i][2] = *(uint32_t*)&As_l[m0][kp + 8];
            Al[i][3] = *(uint32_t*)&As_l[m0 + 8][kp + 8];
        }
#pragma unroll
        for (int j = 0; j < 4; j++) {
            int n0 = wn + j * 8 + grp;
            Bh[j][0] = *(uint32_t*)&Bs_h[n0][kp];
            Bh[j][1] = *(uint32_t*)&Bs_h[n0][kp + 8];
            Bl[j][0] = *(uint32_t*)&Bs_l[n0][kp];
            Bl[j][1] = *(uint32_t*)&Bs_l[n0][kp + 8];
        }

#pragma unroll
        for (int i = 0; i < 4; i++)
#pragma unroll
            for (int j = 0; j < 4; j++) {
                MMA_BF16(acc[i][j], Ah[i], Bh[j]);
                MMA_BF16(acc[i][j], Ah[i], Bl[j]);
                MMA_BF16(acc[i][j], Al[i], Bh[j]);
            }
        __syncthreads();
    }

    // epilogue
#pragma unroll
    for (int i = 0; i < 4; i++) {
        int row0 = bm + wm + i * 16 + grp;
#pragma unroll
        for (int j = 0; j < 4; j++) {
            int col0 = bn + wn + j * 8 + kp;
            float bx = bias[col0], by = bias[col0 + 1];
            float2 v0, v1;
            v0.x = acc[i][j][0] + bx; v0.y = acc[i][j][1] + by;
            v1.x = acc[i][j][2] + bx; v1.y = acc[i][j][3] + by;
            if (relu) {
                v0.x = fmaxf(v0.x, 0.f); v0.y = fmaxf(v0.y, 0.f);
                v1.x = fmaxf(v1.x, 0.f); v1.y = fmaxf(v1.y, 0.f);
            }
            *(float2*)(C + (size_t)row0 * N + col0) = v0;
            *(float2*)(C + (size_t)(row0 + 8) * N + col0) = v1;
        }
    }
}

// ---------------------------------------------------------------------------
// Attention scores (fp32): per (b,h): S = scale * Q_bh [S,64] @ K_bh^T
// ---------------------------------------------------------------------------
__global__ __launch_bounds__(256, 2)
void attn_scores(const float* __restrict__ Q, const float* __restrict__ K,
                 float* __restrict__ Sc, float scale)
{
    const int bh = blockIdx.z;
    const int b = bh >> 4;
    const int hd = bh & 15;
    const int row0 = blockIdx.y * 64;
    const int col0 = blockIdx.x * 64;
    const float* Qb = Q + (size_t)b * SS * DD + hd * 64;
    const float* Kb = K + (size_t)b * SS * DD + hd * 64;

    __shared__ float Qs[64][64];
    __shared__ float Ks[64][64];
    const int tid = threadIdx.x;
    const int lr = tid >> 4;
    const int lc4 = (tid & 15) << 2;
#pragma unroll
    for (int p = 0; p < 4; p++) {
        int r = lr + p * 16;
        float4 q = *(const float4*)(Qb + (size_t)(row0 + r) * DD + lc4);
        Qs[lc4 + 0][r] = q.x; Qs[lc4 + 1][r] = q.y;
        Qs[lc4 + 2][r] = q.z; Qs[lc4 + 3][r] = q.w;
        float4 k = *(const float4*)(Kb + (size_t)(col0 + r) * DD + lc4);
        Ks[lc4 + 0][r] = k.x; Ks[lc4 + 1][r] = k.y;
        Ks[lc4 + 2][r] = k.z; Ks[lc4 + 3][r] = k.w;
    }
    __syncthreads();

    const int tx = tid & 15, ty = tid >> 4;
    float acc[4][4];
#pragma unroll
    for (int i = 0; i < 4; i++)
#pragma unroll
        for (int j = 0; j < 4; j++) acc[i][j] = 0.f;

#pragma unroll
    for (int k = 0; k < 64; k++) {
        float4 a = *(const float4*)(&Qs[k][ty * 4]);
        float4 bv = *(const float4*)(&Ks[k][tx * 4]);
        float aa[4] = {a.x, a.y, a.z, a.w};
        float bb[4] = {bv.x, bv.y, bv.z, bv.w};
#pragma unroll
        for (int i = 0; i < 4; i++)
#pragma unroll
            for (int j = 0; j < 4; j++)
                acc[i][j] = fmaf(aa[i], bb[j], acc[i][j]);
    }

    float* Sb = Sc + (size_t)bh * SS * SS;
#pragma unroll
    for (int i = 0; i < 4; i++) {
        float4 v;
        v.x = acc[i][0] * scale; v.y = acc[i][1] * scale;
        v.z = acc[i][2] * scale; v.w = acc[i][3] * scale;
        *(float4*)(Sb + (size_t)(row0 + ty * 4 + i) * SS + col0 + tx * 4) = v;
    }
}

// ---------------------------------------------------------------------------
// Row softmax (empathy bias is row-constant -> cancels; skipped).
// ---------------------------------------------------------------------------
__global__ void softmax_rows(float* __restrict__ Sc)
{
    float* p = Sc + (size_t)blockIdx.x * SS;
    const int tid = threadIdx.x;
    __shared__ float red[8];

    float4 x = *(float4*)(p + tid * 4);
    float m = fmaxf(fmaxf(x.x, x.y), fmaxf(x.z, x.w));
#pragma unroll
    for (int o = 16; o; o >>= 1) m = fmaxf(m, __shfl_xor_sync(0xffffffffu, m, o));
    if ((tid & 31) == 0) red[tid >> 5] = m;
    __syncthreads();
    float bm = red[0];
#pragma unroll
    for (int i = 1; i < 8; i++) bm = fmaxf(bm, red[i]);
    __syncthreads();

    x.x = expf(x.x - bm); x.y = expf(x.y - bm);
    x.z = expf(x.z - bm); x.w = expf(x.w - bm);
    float s = x.x + x.y + x.z + x.w;
#pragma unroll
    for (int o = 16; o; o >>= 1) s += __shfl_xor_sync(0xffffffffu, s, o);
    if ((tid & 31) == 0) red[tid >> 5] = s;
    __syncthreads();
    float bs = 0.f;
#pragma unroll
    for (int i = 0; i < 8; i++) bs += red[i];
    float inv = 1.0f / bs;
    x.x *= inv; x.y *= inv; x.z *= inv; x.w *= inv;
    *(float4*)(p + tid * 4) = x;
}

// ---------------------------------------------------------------------------
// attn = P @ V per (b,h) (fp32)
// ---------------------------------------------------------------------------
__global__ __launch_bounds__(256, 2)
void attn_av(const float* __restrict__ P, const float* __restrict__ V,
             float* __restrict__ O)
{
    const int bh = blockIdx.z;
    const int b = bh >> 4;
    const int hd = bh & 15;
    const int row0 = blockIdx.x * 64;
    const float* Pb = P + (size_t)bh * SS * SS;
    const float* Vb = V + (size_t)b * SS * DD + hd * 64;
    float* Ob = O + (size_t)b * SS * DD + hd * 64;

    __shared__ float Ps[32][64];
    __shared__ float Vs[32][64];
    const int tid = threadIdx.x;
    const int lr = tid >> 3;
    const int lk4 = (tid & 7) << 2;
    const int vr = tid >> 4;
    const int vc4 = (tid & 15) << 2;
    const int tx = tid & 15, ty = tid >> 4;

    float acc[4][4];
#pragma unroll
    for (int i = 0; i < 4; i++)
#pragma unroll
        for (int j = 0; j < 4; j++) acc[i][j] = 0.f;

    for (int kk = 0; kk < SS; kk += 32) {
#pragma unroll
        for (int ph = 0; ph < 2; ph++) {
            int r = lr + ph * 32;
            float4 pv = *(const float4*)(Pb + (size_t)(row0 + r) * SS + kk + lk4);
            Ps[lk4 + 0][r] = pv.x; Ps[lk4 + 1][r] = pv.y;
            Ps[lk4 + 2][r] = pv.z; Ps[lk4 + 3][r] = pv.w;
        }
#pragma unroll
        for (int ph = 0; ph < 2; ph++) {
            int r = vr + ph * 16;
            float4 vv = *(const float4*)(Vb + (size_t)(kk + r) * DD + vc4);
            *(float4*)(&Vs[r][vc4]) = vv;
        }
        __syncthreads();
#pragma unroll
        for (int k = 0; k < 32; k++) {
            float4 a = *(const float4*)(&Ps[k][ty * 4]);
            float4 bv = *(const float4*)(&Vs[k][tx * 4]);
            float aa[4] = {a.x, a.y, a.z, a.w};
            float bb[4] = {bv.x, bv.y, bv.z, bv.w};
#pragma unroll
            for (int i = 0; i < 4; i++)
#pragma unroll
                for (int j = 0; j < 4; j++)
                    acc[i][j] = fmaf(aa[i], bb[j], acc[i][j]);
        }
        __syncthreads();
    }

#pragma unroll
    for (int i = 0; i < 4; i++) {
        float4 v = {acc[i][0], acc[i][1], acc[i][2], acc[i][3]};
        *(float4*)(Ob + (size_t)(row0 + ty * 4 + i) * DD + tx * 4) = v;
    }
}

// ---------------------------------------------------------------------------
// Fused residual + LayerNorm
// ---------------------------------------------------------------------------
__global__ void add_ln(float* __restrict__ h, const float* __restrict__ y,
                       const float* __restrict__ g, const float* __restrict__ be)
{
    float* hr = h + (size_t)blockIdx.x * DD;
    const float* yr = y + (size_t)blockIdx.x * DD;
    const int tid = threadIdx.x;
    __shared__ float red[8];

    float4 hv = *(float4*)(hr + tid * 4);
    float4 yv = *(const float4*)(yr + tid * 4);
    float z[4] = {hv.x + yv.x, hv.y + yv.y, hv.z + yv.z, hv.w + yv.w};

    float s = z[0] + z[1] + z[2] + z[3];
#pragma unroll
    for (int o = 16; o; o >>= 1) s += __shfl_xor_sync(0xffffffffu, s, o);
    if ((tid & 31) == 0) red[tid >> 5] = s;
    __syncthreads();
    float tot = 0.f;
#pragma unroll
    for (int i = 0; i < 8; i++) tot += red[i];
    float mean = tot * (1.0f / DD);
    __syncthreads();

    float d0 = z[0] - mean, d1 = z[1] - mean, d2 = z[2] - mean, d3 = z[3] - mean;
    float vs = d0 * d0 + d1 * d1 + d2 * d2 + d3 * d3;
#pragma unroll
    for (int o = 16; o; o >>= 1) vs += __shfl_xor_sync(0xffffffffu, vs, o);
    if ((tid & 31) == 0) red[tid >> 5] = vs;
    __syncthreads();
    float vtot = 0.f;
#pragma unroll
    for (int i = 0; i < 8; i++) vtot += red[i];
    float rstd = rsqrtf(vtot * (1.0f / DD) + 1e-5f);

    float4 gv = *(const float4*)(g + tid * 4);
    float4 bv = *(const float4*)(be + tid * 4);
    float4 o;
    o.x = d0 * rstd * gv.x + bv.x;
    o.y = d1 * rstd * gv.y + bv.y;
    o.z = d2 * rstd * gv.z + bv.z;
    o.w = d3 * rstd * gv.w + bv.w;
    *(float4*)(hr + tid * 4) = o;
}

// ---------------------------------------------------------------------------
// Launch
// ---------------------------------------------------------------------------
extern "C" void kernel_launch(void* const* d_in, const int* in_sizes, int n_in,
                              void* d_out, int out_size)
{
    const int*   x     = (const int*)d_in[0];
    const float* noise = (const float*)d_in[1];
    const float* emb   = (const float*)d_in[2];
    const float* Wq    = (const float*)d_in[3];
    const float* bq    = (const float*)d_in[4];
    const float* Wk    = (const float*)d_in[5];
    const float* bk    = (const float*)d_in[6];
    const float* Wv    = (const float*)d_in[7];
    const float* bv    = (const float*)d_in[8];
    const float* Wo    = (const float*)d_in[9];
    const float* bo    = (const float*)d_in[10];
    const float* W1f   = (const float*)d_in[11];
    const float* b1f   = (const float*)d_in[12];
    const float* W2f   = (const float*)d_in[13];
    const float* b2f   = (const float*)d_in[14];
    const float* g1    = (const float*)d_in[15];
    const float* be1   = (const float*)d_in[16];
    const float* g2    = (const float*)d_in[17];
    const float* be2   = (const float*)d_in[18];
    const float* Wout  = (const float*)d_in[19];
    const float* bout  = (const float*)d_in[20];
    float* out = (float*)d_out;

    float *h, *q, *k, *v, *attn, *t1, *t2, *sc;
    cudaGetSymbolAddress((void**)&h, g_h);
    cudaGetSymbolAddress((void**)&q, g_q);
    cudaGetSymbolAddress((void**)&k, g_k);
    cudaGetSymbolAddress((void**)&v, g_v);
    cudaGetSymbolAddress((void**)&attn, g_attn);
    cudaGetSymbolAddress((void**)&t1, g_t1);
    cudaGetSymbolAddress((void**)&t2, g_t2);
    cudaGetSymbolAddress((void**)&sc, g_scores);

    embed_kernel<<<(MTOK * DD) / 256, 256>>>(x, noise, emb, h);

    const float scale = 0.125f; // 1/sqrt(64)

    for (int i = 0; i < LL; i++) {
        const float* Wq_i = Wq + (size_t)i * DD * DD;
        const float* Wk_i = Wk + (size_t)i * DD * DD;
        const float* Wv_i = Wv + (size_t)i * DD * DD;
        const float* Wo_i = Wo + (size_t)i * DD * DD;
        const float* W1_i = W1f + (size_t)i * DD * FFF;
        const float* W2_i = W2f + (size_t)i * FFF * DD;

        bgemm128<<<dim3(DD / 128, MTOK / 128), 256>>>(h, Wq_i, bq + i * DD, q, MTOK, DD, DD, 0);
        bgemm128<<<dim3(DD / 128, MTOK / 128), 256>>>(h, Wk_i, bk + i * DD, k, MTOK, DD, DD, 0);
        bgemm128<<<dim3(DD / 128, MTOK / 128), 256>>>(h, Wv_i, bv + i * DD, v, MTOK, DD, DD, 0);

        attn_scores<<<dim3(SS / 64, SS / 64, BB * HH), 256>>>(q, k, sc, scale);
        softmax_rows<<<BB * HH * SS, 256>>>(sc);
        attn_av<<<dim3(SS / 64, 1, BB * HH), 256>>>(sc, v, attn);

        bgemm128<<<dim3(DD / 128, MTOK / 128), 256>>>(attn, Wo_i, bo + i * DD, t2, MTOK, DD, DD, 0);
        add_ln<<<MTOK, 256>>>(h, t2, g1 + i * DD, be1 + i * DD);

        bgemm128<<<dim3(FFF / 128, MTOK / 128), 256>>>(h, W1_i, b1f + i * FFF, t1, MTOK, FFF, DD, 1);
        bgemm128<<<dim3(DD / 128, MTOK / 128), 256>>>(t1, W2_i, b2f + i * DD, t2, MTOK, DD, FFF, 0);
        add_ln<<<MTOK, 256>>>(h, t2, g2 + i * DD, be2 + i * DD);
    }

    bgemm128<<<dim3(VV / 128, MTOK / 128), 256>>>(h, Wout, bout, out, MTOK, VV, DD, 0);
}

// round 4
// speedup vs baseline: 2.4795x; 1.5599x over previous
#include <cuda_runtime.h>
#include <cuda_bf16.h>
#include <math.h>
#include <stdint.h>

typedef __nv_bfloat16 bf16;

#define BB 2
#define SS 1024
#define DD 1024
#define HH 16
#define LL 3
#define FFF 4096
#define VV 32000
#define MTOK (BB*SS)
#define PHALF ((size_t)BB*HH*SS*SS)

// ------------------------- scratch -------------------------
__device__ float g_h[MTOK * DD];
__device__ float g_t2[MTOK * DD];
__device__ float g_scores[(size_t)BB * HH * SS * SS];

__device__ bf16 s_h[2 * MTOK * DD];
__device__ bf16 s_q[2 * MTOK * DD];
__device__ bf16 s_k[2 * MTOK * DD];
__device__ bf16 s_v[2 * MTOK * DD];
__device__ bf16 s_attn[2 * MTOK * DD];
__device__ bf16 s_t1[2 * MTOK * FFF];
__device__ bf16 s_P[2 * PHALF];

__device__ bf16 s_wq[2 * LL * DD * DD];
__device__ bf16 s_wk[2 * LL * DD * DD];
__device__ bf16 s_wv[2 * LL * DD * DD];
__device__ bf16 s_wo[2 * LL * DD * DD];
__device__ bf16 s_w1[2 * LL * DD * FFF];
__device__ bf16 s_w2[2 * LL * FFF * DD];
__device__ bf16 s_wout[2 * DD * VV];

// ------------------------- helpers -------------------------
__device__ __forceinline__ uint32_t pack_hi2(float x, float y) {
    __nv_bfloat162 v = __halves2bfloat162(__float2bfloat16_rn(x), __float2bfloat16_rn(y));
    return *reinterpret_cast<uint32_t*>(&v);
}
__device__ __forceinline__ uint32_t pack_lo2(float x, float y) {
    float rx = x - __bfloat162float(__float2bfloat16_rn(x));
    float ry = y - __bfloat162float(__float2bfloat16_rn(y));
    __nv_bfloat162 v = __halves2bfloat162(__float2bfloat16_rn(rx), __float2bfloat16_rn(ry));
    return *reinterpret_cast<uint32_t*>(&v);
}
__device__ __forceinline__ uint32_t cvta_smem(const void* p) {
    return (uint32_t)__cvta_generic_to_shared(p);
}
__device__ __forceinline__ void cp16(uint32_t dst, const void* src) {
    asm volatile("cp.async.cg.shared.global [%0], [%1], 16;" :: "r"(dst), "l"(src) : "memory");
}
__device__ __forceinline__ void cp_commit() { asm volatile("cp.async.commit_group;" ::: "memory"); }
__device__ __forceinline__ void cp_wait0()  { asm volatile("cp.async.wait_group 0;" ::: "memory"); }
__device__ __forceinline__ void ldm4(uint32_t* r, uint32_t a) {
    asm volatile("ldmatrix.sync.aligned.m8n8.x4.shared.b16 {%0,%1,%2,%3}, [%4];"
                 : "=r"(r[0]), "=r"(r[1]), "=r"(r[2]), "=r"(r[3]) : "r"(a));
}
__device__ __forceinline__ void ldm4t(uint32_t* r, uint32_t a) {
    asm volatile("ldmatrix.sync.aligned.m8n8.x4.trans.shared.b16 {%0,%1,%2,%3}, [%4];"
                 : "=r"(r[0]), "=r"(r[1]), "=r"(r[2]), "=r"(r[3]) : "r"(a));
}
#define MMA_BF16(c, a, b)                                                     \
    asm volatile("mma.sync.aligned.m16n8k16.row.col.f32.bf16.bf16.f32 "       \
                 "{%0,%1,%2,%3}, {%4,%5,%6,%7}, {%8,%9}, {%0,%1,%2,%3};"      \
                 : "+f"(c[0]), "+f"(c[1]), "+f"(c[2]), "+f"(c[3])             \
                 : "r"(a[0]), "r"(a[1]), "r"(a[2]), "r"(a[3]),                \
                   "r"(b[0]), "r"(b[1]))

// ------------------------- split fp32 -> hi/lo planes -------------------------
__global__ void split_kernel(const float* __restrict__ in, bf16* __restrict__ out, int n)
{
    int i4 = (blockIdx.x * blockDim.x + threadIdx.x) * 4;
    if (i4 >= n) return;
    float4 v = *(const float4*)(in + i4);
    *(uint32_t*)(out + i4)         = pack_hi2(v.x, v.y);
    *(uint32_t*)(out + i4 + 2)     = pack_hi2(v.z, v.w);
    *(uint32_t*)(out + n + i4)     = pack_lo2(v.x, v.y);
    *(uint32_t*)(out + n + i4 + 2) = pack_lo2(v.z, v.w);
}

// ------------------------- embedding -------------------------
__global__ void embed_kernel(const int* __restrict__ x, const float* __restrict__ noise,
                             const float* __restrict__ emb, float* __restrict__ h,
                             bf16* __restrict__ sh)
{
    int i4 = (blockIdx.x * blockDim.x + threadIdx.x) * 4;
    int tok = i4 >> 10, d = i4 & 1023;
    float4 e = *(const float4*)(emb + (size_t)x[tok] * DD + d);
    float4 nz = *(const float4*)(noise + i4);
    float4 v = {e.x + 0.05f*nz.x, e.y + 0.05f*nz.y, e.z + 0.05f*nz.z, e.w + 0.05f*nz.w};
    *(float4*)(h + i4) = v;
    *(uint32_t*)(sh + i4)                 = pack_hi2(v.x, v.y);
    *(uint32_t*)(sh + i4 + 2)             = pack_hi2(v.z, v.w);
    *(uint32_t*)(sh + MTOK*DD + i4)       = pack_lo2(v.x, v.y);
    *(uint32_t*)(sh + MTOK*DD + i4 + 2)   = pack_lo2(v.z, v.w);
}

// ------------------------- tensor-core split GEMM -------------------------
// A [M][K] hi/lo planes. BLAYOUT 0: B [K][N]; BLAYOUT 1: B [N][K] (needs BN=128).
// Batched via blockIdx.z: zb=z>>4, zh=z&15.
template<int BM, int BN, int WARPS_M, int WARPS_N, int BLAYOUT>
__global__ __launch_bounds__(256, 2)
void gemm_tc(const bf16* __restrict__ Ahi, const bf16* __restrict__ Alo, int lda,
             long sAb, long sAh,
             const bf16* __restrict__ Bhi, const bf16* __restrict__ Blo, int ldb,
             long sBb, long sBh,
             float* __restrict__ Cf, bf16* __restrict__ Chi, bf16* __restrict__ Clo,
             int ldc, long sCb, long sCh,
             const float* __restrict__ bias, float alpha, int relu, int K)
{
    constexpr int BK = 16;
    constexpr int WTM = BM / WARPS_M, WTN = BN / WARPS_N;
    constexpr int IT = WTM / 16, JT = WTN / 8;
    constexpr int APLANE = BM * BK * 2;
    constexpr int BPLANE = (BLAYOUT == 0 ? BK * BN : BN * BK) * 2;
    constexpr int STAGE = 2 * APLANE + 2 * BPLANE;

    __shared__ __align__(16) unsigned char smem[2 * STAGE];

    const int tid = threadIdx.x;
    const int lane = tid & 31, wid = tid >> 5;
    const int wm = wid / WARPS_N, wn = wid % WARPS_N;
    const int bm = blockIdx.y * BM, bn = blockIdx.x * BN;
    const int z = blockIdx.z, zb = z >> 4, zh = z & 15;

    const bf16* gAh = Ahi + (size_t)zb * sAb + (size_t)zh * sAh;
    const bf16* gAl = Alo + (size_t)zb * sAb + (size_t)zh * sAh;
    const bf16* gBh = Bhi + (size_t)zb * sBb + (size_t)zh * sBh;
    const bf16* gBl = Blo + (size_t)zb * sBb + (size_t)zh * sBh;
    const uint32_t s0 = cvta_smem(smem);

    float acc[IT][JT][4] = {};
    const int KT = K / BK;

    auto load_stage = [&](int kt, int st) {
        uint32_t sa_hi = s0 + st * STAGE;
        uint32_t sa_lo = sa_hi + APLANE;
        uint32_t sb_hi = sa_hi + 2 * APLANE;
        uint32_t sb_lo = sb_hi + BPLANE;
        {
            int m = tid >> 1, c = tid & 1;
            uint32_t off = m * 32 + ((c ^ ((m >> 2) & 1)) << 4);
            size_t g = (size_t)(bm + m) * lda + kt * BK + c * 8;
            cp16(sa_hi + off, gAh + g);
            cp16(sa_lo + off, gAl + g);
        }
        if (BLAYOUT == 0) {
            constexpr int CPR = BN / 8;
            if (tid < BK * CPR) {
                int k = tid / CPR, c = tid % CPR;
                uint32_t off = k * (BN * 2) + ((c ^ (k & 7)) << 4);
                size_t g = (size_t)(kt * BK + k) * ldb + bn + c * 8;
                cp16(sb_hi + off, gBh + g);
                cp16(sb_lo + off, gBl + g);
            }
        } else {
            int n = tid >> 1, c = tid & 1;
            uint32_t off = n * 32 + ((c ^ ((n >> 2) & 1)) << 4);
            size_t g = (size_t)(bn + n) * ldb + kt * BK + c * 8;
            cp16(sb_hi + off, gBh + g);
            cp16(sb_lo + off, gBl + g);
        }
        cp_commit();
    };

    load_stage(0, 0);
    const int q8 = lane >> 3, r8 = lane & 7;

    for (int kt = 0; kt < KT; kt++) {
        cp_wait0();
        __syncthreads();
        if (kt + 1 < KT) load_stage(kt + 1, (kt + 1) & 1);

        uint32_t sa_hi = s0 + (kt & 1) * STAGE;
        uint32_t sa_lo = sa_hi + APLANE;
        uint32_t sb_hi = sa_hi + 2 * APLANE;
        uint32_t sb_lo = sb_hi + BPLANE;

        uint32_t ah[IT][4], al[IT][4];
#pragma unroll
        for (int i = 0; i < IT; i++) {
            int row = wm * WTM + i * 16 + ((q8 & 1) << 3) + r8;
            int c = q8 >> 1;
            uint32_t off = row * 32 + ((c ^ ((row >> 2) & 1)) << 4);
            ldm4(ah[i], sa_hi + off);
            ldm4(al[i], sa_lo + off);
        }
        uint32_t bh[JT][2], bl[JT][2];
        if (BLAYOUT == 1) {
#pragma unroll
            for (int jj = 0; jj < JT / 2; jj++) {
                int row = wn * WTN + jj * 16 + ((q8 & 1) << 3) + r8;
                int c = q8 >> 1;
                uint32_t off = row * 32 + ((c ^ ((row >> 2) & 1)) << 4);
                uint32_t r[4];
                ldm4(r, sb_hi + off);
                bh[2*jj][0] = r[0]; bh[2*jj+1][0] = r[1];
                bh[2*jj][1] = r[2]; bh[2*jj+1][1] = r[3];
                ldm4(r, sb_lo + off);
                bl[2*jj][0] = r[0]; bl[2*jj+1][0] = r[1];
                bl[2*jj][1] = r[2]; bl[2*jj+1][1] = r[3];
            }
        } else {
#pragma unroll
            for (int jj = 0; jj < JT / 2; jj++) {
                int krow = ((q8 & 1) << 3) + r8;
                int c = (wn * WTN + jj * 16) / 8 + (q8 >> 1);
                uint32_t off = krow * (BN * 2) + ((c ^ (krow & 7)) << 4);
                uint32_t r[4];
                ldm4t(r, sb_hi + off);
                bh[2*jj][0] = r[0]; bh[2*jj][1] = r[1];
                bh[2*jj+1][0] = r[2]; bh[2*jj+1][1] = r[3];
                ldm4t(r, sb_lo + off);
                bl[2*jj][0] = r[0]; bl[2*jj][1] = r[1];
                bl[2*jj+1][0] = r[2]; bl[2*jj+1][1] = r[3];
            }
        }
#pragma unroll
        for (int i = 0; i < IT; i++)
#pragma unroll
            for (int j = 0; j < JT; j++) {
                MMA_BF16(acc[i][j], ah[i], bh[j]);
                MMA_BF16(acc[i][j], ah[i], bl[j]);
                MMA_BF16(acc[i][j], al[i], bh[j]);
            }
        __syncthreads();
    }

    float* pCf = Cf ? Cf + (size_t)zb * sCb + (size_t)zh * sCh : (float*)0;
    bf16* pChi = Chi ? Chi + (size_t)zb * sCb + (size_t)zh * sCh : (bf16*)0;
    bf16* pClo = Clo ? Clo + (size_t)zb * sCb + (size_t)zh * sCh : (bf16*)0;
    const int grp = lane >> 2, qp = (lane & 3) << 1;
#pragma unroll
    for (int i = 0; i < IT; i++) {
        int r0 = bm + wm * WTM + i * 16 + grp;
#pragma unroll
        for (int j = 0; j < JT; j++) {
            int n0 = bn + wn * WTN + j * 8 + qp;
            float b0 = 0.f, b1 = 0.f;
            if (bias) { b0 = __ldg(bias + n0); b1 = __ldg(bias + n0 + 1); }
            float v00 = (acc[i][j][0] + b0) * alpha;
            float v01 = (acc[i][j][1] + b1) * alpha;
            float v10 = (acc[i][j][2] + b0) * alpha;
            float v11 = (acc[i][j][3] + b1) * alpha;
            if (relu) {
                v00 = fmaxf(v00, 0.f); v01 = fmaxf(v01, 0.f);
                v10 = fmaxf(v10, 0.f); v11 = fmaxf(v11, 0.f);
            }
            size_t o0 = (size_t)r0 * ldc + n0;
            size_t o1 = (size_t)(r0 + 8) * ldc + n0;
            if (pCf) {
                float2 a = {v00, v01}, b = {v10, v11};
                *(float2*)(pCf + o0) = a;
                *(float2*)(pCf + o1) = b;
            }
            if (pChi) {
                *(uint32_t*)(pChi + o0) = pack_hi2(v00, v01);
                *(uint32_t*)(pClo + o0) = pack_lo2(v00, v01);
                *(uint32_t*)(pChi + o1) = pack_hi2(v10, v11);
                *(uint32_t*)(pClo + o1) = pack_lo2(v10, v11);
            }
        }
    }
}

// ------------------------- softmax (bias cancels) -------------------------
__global__ void softmax_split(const float* __restrict__ Sc, bf16* __restrict__ P)
{
    const float* p = Sc + (size_t)blockIdx.x * SS;
    size_t ob = (size_t)blockIdx.x * SS + threadIdx.x * 4;
    const int tid = threadIdx.x;
    __shared__ float red[8];

    float4 x = *(const float4*)(p + tid * 4);
    float m = fmaxf(fmaxf(x.x, x.y), fmaxf(x.z, x.w));
#pragma unroll
    for (int o = 16; o; o >>= 1) m = fmaxf(m, __shfl_xor_sync(0xffffffffu, m, o));
    if ((tid & 31) == 0) red[tid >> 5] = m;
    __syncthreads();
    float bm = red[0];
#pragma unroll
    for (int i = 1; i < 8; i++) bm = fmaxf(bm, red[i]);
    __syncthreads();
    x.x = expf(x.x - bm); x.y = expf(x.y - bm);
    x.z = expf(x.z - bm); x.w = expf(x.w - bm);
    float s = x.x + x.y + x.z + x.w;
#pragma unroll
    for (int o = 16; o; o >>= 1) s += __shfl_xor_sync(0xffffffffu, s, o);
    if ((tid & 31) == 0) red[tid >> 5] = s;
    __syncthreads();
    float bs = 0.f;
#pragma unroll
    for (int i = 0; i < 8; i++) bs += red[i];
    float inv = 1.0f / bs;
    x.x *= inv; x.y *= inv; x.z *= inv; x.w *= inv;
    *(uint32_t*)(P + ob)            = pack_hi2(x.x, x.y);
    *(uint32_t*)(P + ob + 2)        = pack_hi2(x.z, x.w);
    *(uint32_t*)(P + PHALF + ob)     = pack_lo2(x.x, x.y);
    *(uint32_t*)(P + PHALF + ob + 2) = pack_lo2(x.z, x.w);
}

// ------------------------- residual + LayerNorm (+split) -------------------------
__global__ void add_ln(float* __restrict__ h, const float* __restrict__ y,
                       const float* __restrict__ g, const float* __restrict__ be,
                       bf16* __restrict__ sh)
{
    float* hr = h + (size_t)blockIdx.x * DD;
    const float* yr = y + (size_t)blockIdx.x * DD;
    const int tid = threadIdx.x;
    __shared__ float red[8];

    float4 hv = *(float4*)(hr + tid * 4);
    float4 yv = *(const float4*)(yr + tid * 4);
    float z[4] = {hv.x + yv.x, hv.y + yv.y, hv.z + yv.z, hv.w + yv.w};

    float s = z[0] + z[1] + z[2] + z[3];
#pragma unroll
    for (int o = 16; o; o >>= 1) s += __shfl_xor_sync(0xffffffffu, s, o);
    if ((tid & 31) == 0) red[tid >> 5] = s;
    __syncthreads();
    float tot = 0.f;
#pragma unroll
    for (int i = 0; i < 8; i++) tot += red[i];
    float mean = tot * (1.0f / DD);
    __syncthreads();

    float d0 = z[0]-mean, d1 = z[1]-mean, d2 = z[2]-mean, d3 = z[3]-mean;
    float vs = d0*d0 + d1*d1 + d2*d2 + d3*d3;
#pragma unroll
    for (int o = 16; o; o >>= 1) vs += __shfl_xor_sync(0xffffffffu, vs, o);
    if ((tid & 31) == 0) red[tid >> 5] = vs;
    __syncthreads();
    float vtot = 0.f;
#pragma unroll
    for (int i = 0; i < 8; i++) vtot += red[i];
    float rstd = rsqrtf(vtot * (1.0f / DD) + 1e-5f);

    float4 gv = *(const float4*)(g + tid * 4);
    float4 bv = *(const float4*)(be + tid * 4);
    float4 o;
    o.x = d0*rstd*gv.x + bv.x; o.y = d1*rstd*gv.y + bv.y;
    o.z = d2*rstd*gv.z + bv.z; o.w = d3*rstd*gv.w + bv.w;
    *(float4*)(hr + tid * 4) = o;

    size_t ob = (size_t)blockIdx.x * DD + tid * 4;
    *(uint32_t*)(sh + ob)               = pack_hi2(o.x, o.y);
    *(uint32_t*)(sh + ob + 2)           = pack_hi2(o.z, o.w);
    *(uint32_t*)(sh + MTOK*DD + ob)     = pack_lo2(o.x, o.y);
    *(uint32_t*)(sh + MTOK*DD + ob + 2) = pack_lo2(o.z, o.w);
}

// ------------------------- launch -------------------------
extern "C" void kernel_launch(void* const* d_in, const int* in_sizes, int n_in,
                              void* d_out, int out_size)
{
    const int*   x     = (const int*)d_in[0];
    const float* noise = (const float*)d_in[1];
    const float* emb   = (const float*)d_in[2];
    const float* Wq    = (const float*)d_in[3];
    const float* bq    = (const float*)d_in[4];
    const float* Wk    = (const float*)d_in[5];
    const float* bk    = (const float*)d_in[6];
    const float* Wv    = (const float*)d_in[7];
    const float* bv    = (const float*)d_in[8];
    const float* Wo    = (const float*)d_in[9];
    const float* bo    = (const float*)d_in[10];
    const float* W1f   = (const float*)d_in[11];
    const float* b1f   = (const float*)d_in[12];
    const float* W2f   = (const float*)d_in[13];
    const float* b2f   = (const float*)d_in[14];
    const float* g1    = (const float*)d_in[15];
    const float* be1   = (const float*)d_in[16];
    const float* g2    = (const float*)d_in[17];
    const float* be2   = (const float*)d_in[18];
    const float* Wout  = (const float*)d_in[19];
    const float* bout  = (const float*)d_in[20];
    float* out = (float*)d_out;

    float *h, *t2, *sc;
    bf16 *sh, *sq, *sk, *sv, *sat, *st1, *sP;
    bf16 *wq, *wk, *wv, *wo, *w1, *w2, *wout;
    cudaGetSymbolAddress((void**)&h, g_h);
    cudaGetSymbolAddress((void**)&t2, g_t2);
    cudaGetSymbolAddress((void**)&sc, g_scores);
    cudaGetSymbolAddress((void**)&sh, s_h);
    cudaGetSymbolAddress((void**)&sq, s_q);
    cudaGetSymbolAddress((void**)&sk, s_k);
    cudaGetSymbolAddress((void**)&sv, s_v);
    cudaGetSymbolAddress((void**)&sat, s_attn);
    cudaGetSymbolAddress((void**)&st1, s_t1);
    cudaGetSymbolAddress((void**)&sP, s_P);
    cudaGetSymbolAddress((void**)&wq, s_wq);
    cudaGetSymbolAddress((void**)&wk, s_wk);
    cudaGetSymbolAddress((void**)&wv, s_wv);
    cudaGetSymbolAddress((void**)&wo, s_wo);
    cudaGetSymbolAddress((void**)&w1, s_w1);
    cudaGetSymbolAddress((void**)&w2, s_w2);
    cudaGetSymbolAddress((void**)&wout, s_wout);

    const int nQ = LL * DD * DD;       // per-tensor qkv/o element count
    const int nF = LL * DD * FFF;      // ffn weights
    const int nO = DD * VV;            // vocab weight

    split_kernel<<<nQ / 1024, 256>>>(Wq, wq, nQ);
    split_kernel<<<nQ / 1024, 256>>>(Wk, wk, nQ);
    split_kernel<<<nQ / 1024, 256>>>(Wv, wv, nQ);
    split_kernel<<<nQ / 1024, 256>>>(Wo, wo, nQ);
    split_kernel<<<nF / 1024, 256>>>(W1f, w1, nF);
    split_kernel<<<nF / 1024, 256>>>(W2f, w2, nF);
    split_kernel<<<nO / 1024, 256>>>(Wout, wout, nO);

    embed_kernel<<<(MTOK * DD) / 1024, 256>>>(x, noise, emb, h, sh);

    const long HD = (long)MTOK * DD;       // plane size for token-major tensors
    const long TF = (long)MTOK * FFF;

    for (int i = 0; i < LL; i++) {
        const bf16 *wqh = wq + (size_t)i * DD * DD, *wql = wqh + nQ;
        const bf16 *wkh = wk + (size_t)i * DD * DD, *wkl = wkh + nQ;
        const bf16 *wvh = wv + (size_t)i * DD * DD, *wvl = wvh + nQ;
        const bf16 *woh = wo + (size_t)i * DD * DD, *wol = woh + nQ;
        const bf16 *w1h = w1 + (size_t)i * DD * FFF, *w1l = w1h + nF;
        const bf16 *w2h = w2 + (size_t)i * FFF * DD, *w2l = w2h + nF;

        // QKV projections (split-bf16 out)
        gemm_tc<128,128,2,4,0><<<dim3(8,16,1), 256>>>(
            sh, sh+HD, DD, 0,0, wqh, wql, DD, 0,0,
            (float*)0, sq, sq+HD, DD, 0,0, bq + i*DD, 1.f, 0, DD);
        gemm_tc<128,128,2,4,0><<<dim3(8,16,1), 256>>>(
            sh, sh+HD, DD, 0,0, wkh, wkl, DD, 0,0,
            (float*)0, sk, sk+HD, DD, 0,0, bk + i*DD, 1.f, 0, DD);
        gemm_tc<128,128,2,4,0><<<dim3(8,16,1), 256>>>(
            sh, sh+HD, DD, 0,0, wvh, wvl, DD, 0,0,
            (float*)0, sv, sv+HD, DD, 0,0, bv + i*DD, 1.f, 0, DD);

        // scores = 0.125 * Q K^T   (batched over b,h via z)
        gemm_tc<128,128,2,4,1><<<dim3(8,8,32), 256>>>(
            sq, sq+HD, DD, (long)SS*DD, 64, sk, sk+HD, DD, (long)SS*DD, 64,
            sc, (bf16*)0, (bf16*)0, SS, (long)HH*SS*SS, (long)SS*SS,
            (float*)0, 0.125f, 0, 64);

        softmax_split<<<BB*HH*SS, 256>>>(sc, sP);

        // attn = P V
        gemm_tc<128,64,4,2,0><<<dim3(1,8,32), 256>>>(
            sP, sP+PHALF, SS, (long)HH*SS*SS, (long)SS*SS,
            sv, sv+HD, DD, (long)SS*DD, 64,
            (float*)0, sat, sat+HD, DD, (long)SS*DD, 64,
            (float*)0, 1.f, 0, SS);

        // output projection -> fp32 t2
        gemm_tc<128,128,2,4,0><<<dim3(8,16,1), 256>>>(
            sat, sat+HD, DD, 0,0, woh, wol, DD, 0,0,
            t2, (bf16*)0, (bf16*)0, DD, 0,0, bo + i*DD, 1.f, 0, DD);
        add_ln<<<MTOK, 256>>>(h, t2, g1 + i*DD, be1 + i*DD, sh);

        // FFN
        gemm_tc<128,128,2,4,0><<<dim3(32,16,1), 256>>>(
            sh, sh+HD, DD, 0,0, w1h, w1l, FFF, 0,0,
            (float*)0, st1, st1+TF, FFF, 0,0, b1f + i*FFF, 1.f, 1, DD);
        gemm_tc<128,128,2,4,0><<<dim3(8,16,1), 256>>>(
            st1, st1+TF, FFF, 0,0, w2h, w2l, DD, 0,0,
            t2, (bf16*)0, (bf16*)0, DD, 0,0, b2f + i*DD, 1.f, 0, FFF);
        add_ln<<<MTOK, 256>>>(h, t2, g2 + i*DD, be2 + i*DD, sh);
    }

    // vocab projection
    gemm_tc<128,128,2,4,0><<<dim3(250,16,1), 256>>>(
        sh, sh+HD, DD, 0,0, wout, wout + nO, VV, 0,0,
        out, (bf16*)0, (bf16*)0, VV, 0,0, bout, 1.f, 0, DD);
}

// round 5
// speedup vs baseline: 2.7038x; 1.0905x over previous
#include <cuda_runtime.h>
#include <cuda_bf16.h>
#include <math.h>
#include <stdint.h>

typedef __nv_bfloat16 bf16;

#define BB 2
#define SS 1024
#define DD 1024
#define HH 16
#define LL 3
#define FFF 4096
#define VV 32000
#define MTOK (BB*SS)
#define PHALF ((size_t)BB*HH*SS*SS)

// ------------------------- scratch -------------------------
__device__ float g_h[MTOK * DD];
__device__ float g_t2[MTOK * DD];
__device__ float g_scores[(size_t)BB * HH * SS * SS];

__device__ bf16 s_h[2 * MTOK * DD];
__device__ bf16 s_q[2 * MTOK * DD];
__device__ bf16 s_k[2 * MTOK * DD];
__device__ bf16 s_v[2 * MTOK * DD];
__device__ bf16 s_attn[2 * MTOK * DD];
__device__ bf16 s_t1[2 * MTOK * FFF];
__device__ bf16 s_P[2 * PHALF];

__device__ bf16 s_wq[2 * LL * DD * DD];
__device__ bf16 s_wk[2 * LL * DD * DD];
__device__ bf16 s_wv[2 * LL * DD * DD];
__device__ bf16 s_wo[2 * LL * DD * DD];
__device__ bf16 s_w1[2 * LL * DD * FFF];
__device__ bf16 s_w2[2 * LL * FFF * DD];
__device__ bf16 s_wout[2 * DD * VV];

// ------------------------- helpers -------------------------
__device__ __forceinline__ uint32_t pack_hi2(float x, float y) {
    __nv_bfloat162 v = __halves2bfloat162(__float2bfloat16_rn(x), __float2bfloat16_rn(y));
    return *reinterpret_cast<uint32_t*>(&v);
}
__device__ __forceinline__ uint32_t pack_lo2(float x, float y) {
    float rx = x - __bfloat162float(__float2bfloat16_rn(x));
    float ry = y - __bfloat162float(__float2bfloat16_rn(y));
    __nv_bfloat162 v = __halves2bfloat162(__float2bfloat16_rn(rx), __float2bfloat16_rn(ry));
    return *reinterpret_cast<uint32_t*>(&v);
}
__device__ __forceinline__ uint32_t cvta_smem(const void* p) {
    return (uint32_t)__cvta_generic_to_shared(p);
}
__device__ __forceinline__ void cp16(uint32_t dst, const void* src) {
    asm volatile("cp.async.cg.shared.global [%0], [%1], 16;" :: "r"(dst), "l"(src) : "memory");
}
__device__ __forceinline__ void cp_commit() { asm volatile("cp.async.commit_group;" ::: "memory"); }
__device__ __forceinline__ void cp_wait0()  { asm volatile("cp.async.wait_group 0;" ::: "memory"); }
__device__ __forceinline__ void cp_wait1()  { asm volatile("cp.async.wait_group 1;" ::: "memory"); }
__device__ __forceinline__ void ldm4(uint32_t* r, uint32_t a) {
    asm volatile("ldmatrix.sync.aligned.m8n8.x4.shared.b16 {%0,%1,%2,%3}, [%4];"
                 : "=r"(r[0]), "=r"(r[1]), "=r"(r[2]), "=r"(r[3]) : "r"(a));
}
__device__ __forceinline__ void ldm4t(uint32_t* r, uint32_t a) {
    asm volatile("ldmatrix.sync.aligned.m8n8.x4.trans.shared.b16 {%0,%1,%2,%3}, [%4];"
                 : "=r"(r[0]), "=r"(r[1]), "=r"(r[2]), "=r"(r[3]) : "r"(a));
}
#define MMA_BF16(c, a, b)                                                     \
    asm volatile("mma.sync.aligned.m16n8k16.row.col.f32.bf16.bf16.f32 "       \
                 "{%0,%1,%2,%3}, {%4,%5,%6,%7}, {%8,%9}, {%0,%1,%2,%3};"      \
                 : "+f"(c[0]), "+f"(c[1]), "+f"(c[2]), "+f"(c[3])             \
                 : "r"(a[0]), "r"(a[1]), "r"(a[2]), "r"(a[3]),                \
                   "r"(b[0]), "r"(b[1]))

// ------------------------- split fp32 -> hi/lo planes -------------------------
__global__ void split_kernel(const float* __restrict__ in, bf16* __restrict__ out, int n)
{
    int i4 = (blockIdx.x * blockDim.x + threadIdx.x) * 4;
    if (i4 >= n) return;
    float4 v = *(const float4*)(in + i4);
    *(uint32_t*)(out + i4)         = pack_hi2(v.x, v.y);
    *(uint32_t*)(out + i4 + 2)     = pack_hi2(v.z, v.w);
    *(uint32_t*)(out + n + i4)     = pack_lo2(v.x, v.y);
    *(uint32_t*)(out + n + i4 + 2) = pack_lo2(v.z, v.w);
}

// ------------------------- embedding -------------------------
__global__ void embed_kernel(const int* __restrict__ x, const float* __restrict__ noise,
                             const float* __restrict__ emb, float* __restrict__ h,
                             bf16* __restrict__ sh)
{
    int i4 = (blockIdx.x * blockDim.x + threadIdx.x) * 4;
    int tok = i4 >> 10, d = i4 & 1023;
    float4 e = *(const float4*)(emb + (size_t)x[tok] * DD + d);
    float4 nz = *(const float4*)(noise + i4);
    float4 v = {e.x + 0.05f*nz.x, e.y + 0.05f*nz.y, e.z + 0.05f*nz.z, e.w + 0.05f*nz.w};
    *(float4*)(h + i4) = v;
    *(uint32_t*)(sh + i4)                 = pack_hi2(v.x, v.y);
    *(uint32_t*)(sh + i4 + 2)             = pack_hi2(v.z, v.w);
    *(uint32_t*)(sh + MTOK*DD + i4)       = pack_lo2(v.x, v.y);
    *(uint32_t*)(sh + MTOK*DD + i4 + 2)   = pack_lo2(v.z, v.w);
}

// ------------------------- tensor-core split GEMM, 3-stage pipeline ---------
// A [M][K] hi/lo planes. BLAYOUT 0: B [K][N]; BLAYOUT 1: B [N][K] (needs BN=128).
// Batched via blockIdx.z: zb=z>>4, zh=z&15.
template<int BM, int BN, int WARPS_M, int WARPS_N, int BLAYOUT>
__global__ __launch_bounds__(256, 2)
void gemm_tc(const bf16* __restrict__ Ahi, const bf16* __restrict__ Alo, int lda,
             long sAb, long sAh,
             const bf16* __restrict__ Bhi, const bf16* __restrict__ Blo, int ldb,
             long sBb, long sBh,
             float* __restrict__ Cf, bf16* __restrict__ Chi, bf16* __restrict__ Clo,
             int ldc, long sCb, long sCh,
             const float* __restrict__ bias, float alpha, int relu, int K)
{
    constexpr int BK = 16;
    constexpr int STAGES = 3;
    constexpr int WTM = BM / WARPS_M, WTN = BN / WARPS_N;
    constexpr int IT = WTM / 16, JT = WTN / 8;
    constexpr int APLANE = BM * BK * 2;
    constexpr int BPLANE = (BLAYOUT == 0 ? BK * BN : BN * BK) * 2;
    constexpr int STAGE = 2 * APLANE + 2 * BPLANE;

    __shared__ __align__(16) unsigned char smem[STAGES * STAGE];

    const int tid = threadIdx.x;
    const int lane = tid & 31, wid = tid >> 5;
    const int wm = wid / WARPS_N, wn = wid % WARPS_N;
    const int bm = blockIdx.y * BM, bn = blockIdx.x * BN;
    const int z = blockIdx.z, zb = z >> 4, zh = z & 15;

    const bf16* gAh = Ahi + (size_t)zb * sAb + (size_t)zh * sAh;
    const bf16* gAl = Alo + (size_t)zb * sAb + (size_t)zh * sAh;
    const bf16* gBh = Bhi + (size_t)zb * sBb + (size_t)zh * sBh;
    const bf16* gBl = Blo + (size_t)zb * sBb + (size_t)zh * sBh;
    const uint32_t s0 = cvta_smem(smem);

    float acc[IT][JT][4] = {};
    const int KT = K / BK;

    auto load_stage = [&](int kt, int st) {
        uint32_t sa_hi = s0 + st * STAGE;
        uint32_t sa_lo = sa_hi + APLANE;
        uint32_t sb_hi = sa_hi + 2 * APLANE;
        uint32_t sb_lo = sb_hi + BPLANE;
        {
            int m = tid >> 1, c = tid & 1;
            uint32_t off = m * 32 + ((c ^ ((m >> 2) & 1)) << 4);
            size_t g = (size_t)(bm + m) * lda + kt * BK + c * 8;
            cp16(sa_hi + off, gAh + g);
            cp16(sa_lo + off, gAl + g);
        }
        if (BLAYOUT == 0) {
            constexpr int CPR = BN / 8;
            if (tid < BK * CPR) {
                int k = tid / CPR, c = tid % CPR;
                uint32_t off = k * (BN * 2) + ((c ^ (k & 7)) << 4);
                size_t g = (size_t)(kt * BK + k) * ldb + bn + c * 8;
                cp16(sb_hi + off, gBh + g);
                cp16(sb_lo + off, gBl + g);
            }
        } else {
            int n = tid >> 1, c = tid & 1;
            uint32_t off = n * 32 + ((c ^ ((n >> 2) & 1)) << 4);
            size_t g = (size_t)(bn + n) * ldb + kt * BK + c * 8;
            cp16(sb_hi + off, gBh + g);
            cp16(sb_lo + off, gBl + g);
        }
        cp_commit();
    };

    load_stage(0, 0);
    if (KT > 1) load_stage(1, 1);
    const int q8 = lane >> 3, r8 = lane & 7;

    for (int kt = 0; kt < KT; kt++) {
        if (kt + 1 < KT) cp_wait1(); else cp_wait0();
        __syncthreads();
        if (kt + 2 < KT) load_stage(kt + 2, (kt + 2) % STAGES);

        uint32_t sa_hi = s0 + (kt % STAGES) * STAGE;
        uint32_t sa_lo = sa_hi + APLANE;
        uint32_t sb_hi = sa_hi + 2 * APLANE;
        uint32_t sb_lo = sb_hi + BPLANE;

        uint32_t ah[IT][4], al[IT][4];
#pragma unroll
        for (int i = 0; i < IT; i++) {
            int row = wm * WTM + i * 16 + ((q8 & 1) << 3) + r8;
            int c = q8 >> 1;
            uint32_t off = row * 32 + ((c ^ ((row >> 2) & 1)) << 4);
            ldm4(ah[i], sa_hi + off);
            ldm4(al[i], sa_lo + off);
        }
        uint32_t bh[JT][2], bl[JT][2];
        if (BLAYOUT == 1) {
#pragma unroll
            for (int jj = 0; jj < JT / 2; jj++) {
                int row = wn * WTN + jj * 16 + ((q8 & 1) << 3) + r8;
                int c = q8 >> 1;
                uint32_t off = row * 32 + ((c ^ ((row >> 2) & 1)) << 4);
                uint32_t r[4];
                ldm4(r, sb_hi + off);
                bh[2*jj][0] = r[0]; bh[2*jj+1][0] = r[1];
                bh[2*jj][1] = r[2]; bh[2*jj+1][1] = r[3];
                ldm4(r, sb_lo + off);
                bl[2*jj][0] = r[0]; bl[2*jj+1][0] = r[1];
                bl[2*jj][1] = r[2]; bl[2*jj+1][1] = r[3];
            }
        } else {
#pragma unroll
            for (int jj = 0; jj < JT / 2; jj++) {
                int krow = ((q8 & 1) << 3) + r8;
                int c = (wn * WTN + jj * 16) / 8 + (q8 >> 1);
                uint32_t off = krow * (BN * 2) + ((c ^ (krow & 7)) << 4);
                uint32_t r[4];
                ldm4t(r, sb_hi + off);
                bh[2*jj][0] = r[0]; bh[2*jj][1] = r[1];
                bh[2*jj+1][0] = r[2]; bh[2*jj+1][1] = r[3];
                ldm4t(r, sb_lo + off);
                bl[2*jj][0] = r[0]; bl[2*jj][1] = r[1];
                bl[2*jj+1][0] = r[2]; bl[2*jj+1][1] = r[3];
            }
        }
#pragma unroll
        for (int i = 0; i < IT; i++)
#pragma unroll
            for (int j = 0; j < JT; j++) {
                MMA_BF16(acc[i][j], ah[i], bh[j]);
                MMA_BF16(acc[i][j], ah[i], bl[j]);
                MMA_BF16(acc[i][j], al[i], bh[j]);
            }
    }

    float* pCf = Cf ? Cf + (size_t)zb * sCb + (size_t)zh * sCh : (float*)0;
    bf16* pChi = Chi ? Chi + (size_t)zb * sCb + (size_t)zh * sCh : (bf16*)0;
    bf16* pClo = Clo ? Clo + (size_t)zb * sCb + (size_t)zh * sCh : (bf16*)0;
    const int grp = lane >> 2, qp = (lane & 3) << 1;
#pragma unroll
    for (int i = 0; i < IT; i++) {
        int r0 = bm + wm * WTM + i * 16 + grp;
#pragma unroll
        for (int j = 0; j < JT; j++) {
            int n0 = bn + wn * WTN + j * 8 + qp;
            float b0 = 0.f, b1 = 0.f;
            if (bias) { b0 = __ldg(bias + n0); b1 = __ldg(bias + n0 + 1); }
            float v00 = (acc[i][j][0] + b0) * alpha;
            float v01 = (acc[i][j][1] + b1) * alpha;
            float v10 = (acc[i][j][2] + b0) * alpha;
            float v11 = (acc[i][j][3] + b1) * alpha;
            if (relu) {
                v00 = fmaxf(v00, 0.f); v01 = fmaxf(v01, 0.f);
                v10 = fmaxf(v10, 0.f); v11 = fmaxf(v11, 0.f);
            }
            size_t o0 = (size_t)r0 * ldc + n0;
            size_t o1 = (size_t)(r0 + 8) * ldc + n0;
            if (pCf) {
                float2 a = {v00, v01}, b = {v10, v11};
                *(float2*)(pCf + o0) = a;
                *(float2*)(pCf + o1) = b;
            }
            if (pChi) {
                *(uint32_t*)(pChi + o0) = pack_hi2(v00, v01);
                *(uint32_t*)(pClo + o0) = pack_lo2(v00, v01);
                *(uint32_t*)(pChi + o1) = pack_hi2(v10, v11);
                *(uint32_t*)(pClo + o1) = pack_lo2(v10, v11);
            }
        }
    }
}

// ------------------------- softmax (bias cancels) -------------------------
__global__ void softmax_split(const float* __restrict__ Sc, bf16* __restrict__ P)
{
    const float* p = Sc + (size_t)blockIdx.x * SS;
    size_t ob = (size_t)blockIdx.x * SS + threadIdx.x * 4;
    const int tid = threadIdx.x;
    __shared__ float red[8];

    float4 x = *(const float4*)(p + tid * 4);
    float m = fmaxf(fmaxf(x.x, x.y), fmaxf(x.z, x.w));
#pragma unroll
    for (int o = 16; o; o >>= 1) m = fmaxf(m, __shfl_xor_sync(0xffffffffu, m, o));
    if ((tid & 31) == 0) red[tid >> 5] = m;
    __syncthreads();
    float bm = red[0];
#pragma unroll
    for (int i = 1; i < 8; i++) bm = fmaxf(bm, red[i]);
    __syncthreads();
    x.x = expf(x.x - bm); x.y = expf(x.y - bm);
    x.z = expf(x.z - bm); x.w = expf(x.w - bm);
    float s = x.x + x.y + x.z + x.w;
#pragma unroll
    for (int o = 16; o; o >>= 1) s += __shfl_xor_sync(0xffffffffu, s, o);
    if ((tid & 31) == 0) red[tid >> 5] = s;
    __syncthreads();
    float bs = 0.f;
#pragma unroll
    for (int i = 0; i < 8; i++) bs += red[i];
    float inv = 1.0f / bs;
    x.x *= inv; x.y *= inv; x.z *= inv; x.w *= inv;
    *(uint32_t*)(P + ob)             = pack_hi2(x.x, x.y);
    *(uint32_t*)(P + ob + 2)         = pack_hi2(x.z, x.w);
    *(uint32_t*)(P + PHALF + ob)     = pack_lo2(x.x, x.y);
    *(uint32_t*)(P + PHALF + ob + 2) = pack_lo2(x.z, x.w);
}

// ------------------------- residual + LayerNorm (+split) -------------------------
__global__ void add_ln(float* __restrict__ h, const float* __restrict__ y,
                       const float* __restrict__ g, const float* __restrict__ be,
                       bf16* __restrict__ sh)
{
    float* hr = h + (size_t)blockIdx.x * DD;
    const float* yr = y + (size_t)blockIdx.x * DD;
    const int tid = threadIdx.x;
    __shared__ float red[8];

    float4 hv = *(float4*)(hr + tid * 4);
    float4 yv = *(const float4*)(yr + tid * 4);
    float z[4] = {hv.x + yv.x, hv.y + yv.y, hv.z + yv.z, hv.w + yv.w};

    float s = z[0] + z[1] + z[2] + z[3];
#pragma unroll
    for (int o = 16; o; o >>= 1) s += __shfl_xor_sync(0xffffffffu, s, o);
    if ((tid & 31) == 0) red[tid >> 5] = s;
    __syncthreads();
    float tot = 0.f;
#pragma unroll
    for (int i = 0; i < 8; i++) tot += red[i];
    float mean = tot * (1.0f / DD);
    __syncthreads();

    float d0 = z[0]-mean, d1 = z[1]-mean, d2 = z[2]-mean, d3 = z[3]-mean;
    float vs = d0*d0 + d1*d1 + d2*d2 + d3*d3;
#pragma unroll
    for (int o = 16; o; o >>= 1) vs += __shfl_xor_sync(0xffffffffu, vs, o);
    if ((tid & 31) == 0) red[tid >> 5] = vs;
    __syncthreads();
    float vtot = 0.f;
#pragma unroll
    for (int i = 0; i < 8; i++) vtot += red[i];
    float rstd = rsqrtf(vtot * (1.0f / DD) + 1e-5f);

    float4 gv = *(const float4*)(g + tid * 4);
    float4 bv = *(const float4*)(be + tid * 4);
    float4 o;
    o.x = d0*rstd*gv.x + bv.x; o.y = d1*rstd*gv.y + bv.y;
    o.z = d2*rstd*gv.z + bv.z; o.w = d3*rstd*gv.w + bv.w;
    *(float4*)(hr + tid * 4) = o;

    size_t ob = (size_t)blockIdx.x * DD + tid * 4;
    *(uint32_t*)(sh + ob)               = pack_hi2(o.x, o.y);
    *(uint32_t*)(sh + ob + 2)           = pack_hi2(o.z, o.w);
    *(uint32_t*)(sh + MTOK*DD + ob)     = pack_lo2(o.x, o.y);
    *(uint32_t*)(sh + MTOK*DD + ob + 2) = pack_lo2(o.z, o.w);
}

// ------------------------- launch -------------------------
extern "C" void kernel_launch(void* const* d_in, const int* in_sizes, int n_in,
                              void* d_out, int out_size)
{
    const int*   x     = (const int*)d_in[0];
    const float* noise = (const float*)d_in[1];
    const float* emb   = (const float*)d_in[2];
    const float* Wq    = (const float*)d_in[3];
    const float* bq    = (const float*)d_in[4];
    const float* Wk    = (const float*)d_in[5];
    const float* bk    = (const float*)d_in[6];
    const float* Wv    = (const float*)d_in[7];
    const float* bv    = (const float*)d_in[8];
    const float* Wo    = (const float*)d_in[9];
    const float* bo    = (const float*)d_in[10];
    const float* W1f   = (const float*)d_in[11];
    const float* b1f   = (const float*)d_in[12];
    const float* W2f   = (const float*)d_in[13];
    const float* b2f   = (const float*)d_in[14];
    const float* g1    = (const float*)d_in[15];
    const float* be1   = (const float*)d_in[16];
    const float* g2    = (const float*)d_in[17];
    const float* be2   = (const float*)d_in[18];
    const float* Wout  = (const float*)d_in[19];
    const float* bout  = (const float*)d_in[20];
    float* out = (float*)d_out;

    float *h, *t2, *sc;
    bf16 *sh, *sq, *sk, *sv, *sat, *st1, *sP;
    bf16 *wq, *wk, *wv, *wo, *w1, *w2, *wout;
    cudaGetSymbolAddress((void**)&h, g_h);
    cudaGetSymbolAddress((void**)&t2, g_t2);
    cudaGetSymbolAddress((void**)&sc, g_scores);
    cudaGetSymbolAddress((void**)&sh, s_h);
    cudaGetSymbolAddress((void**)&sq, s_q);
    cudaGetSymbolAddress((void**)&sk, s_k);
    cudaGetSymbolAddress((void**)&sv, s_v);
    cudaGetSymbolAddress((void**)&sat, s_attn);
    cudaGetSymbolAddress((void**)&st1, s_t1);
    cudaGetSymbolAddress((void**)&sP, s_P);
    cudaGetSymbolAddress((void**)&wq, s_wq);
    cudaGetSymbolAddress((void**)&wk, s_wk);
    cudaGetSymbolAddress((void**)&wv, s_wv);
    cudaGetSymbolAddress((void**)&wo, s_wo);
    cudaGetSymbolAddress((void**)&w1, s_w1);
    cudaGetSymbolAddress((void**)&w2, s_w2);
    cudaGetSymbolAddress((void**)&wout, s_wout);

    const int nQ = LL * DD * DD;
    const int nF = LL * DD * FFF;
    const int nO = DD * VV;

    split_kernel<<<nQ / 1024, 256>>>(Wq, wq, nQ);
    split_kernel<<<nQ / 1024, 256>>>(Wk, wk, nQ);
    split_kernel<<<nQ / 1024, 256>>>(Wv, wv, nQ);
    split_kernel<<<nQ / 1024, 256>>>(Wo, wo, nQ);
    split_kernel<<<nF / 1024, 256>>>(W1f, w1, nF);
    split_kernel<<<nF / 1024, 256>>>(W2f, w2, nF);
    split_kernel<<<nO / 1024, 256>>>(Wout, wout, nO);

    embed_kernel<<<(MTOK * DD) / 1024, 256>>>(x, noise, emb, h, sh);

    const long HD = (long)MTOK * DD;
    const long TF = (long)MTOK * FFF;

    for (int i = 0; i < LL; i++) {
        const bf16 *wqh = wq + (size_t)i * DD * DD, *wql = wqh + nQ;
        const bf16 *wkh = wk + (size_t)i * DD * DD, *wkl = wkh + nQ;
        const bf16 *wvh = wv + (size_t)i * DD * DD, *wvl = wvh + nQ;
        const bf16 *woh = wo + (size_t)i * DD * DD, *wol = woh + nQ;
        const bf16 *w1h = w1 + (size_t)i * DD * FFF, *w1l = w1h + nF;
        const bf16 *w2h = w2 + (size_t)i * FFF * DD, *w2l = w2h + nF;

        gemm_tc<128,128,2,4,0><<<dim3(8,16,1), 256>>>(
            sh, sh+HD, DD, 0,0, wqh, wql, DD, 0,0,
            (float*)0, sq, sq+HD, DD, 0,0, bq + i*DD, 1.f, 0, DD);
        gemm_tc<128,128,2,4,0><<<dim3(8,16,1), 256>>>(
            sh, sh+HD, DD, 0,0, wkh, wkl, DD, 0,0,
            (float*)0, sk, sk+HD, DD, 0,0, bk + i*DD, 1.f, 0, DD);
        gemm_tc<128,128,2,4,0><<<dim3(8,16,1), 256>>>(
            sh, sh+HD, DD, 0,0, wvh, wvl, DD, 0,0,
            (float*)0, sv, sv+HD, DD, 0,0, bv + i*DD, 1.f, 0, DD);

        gemm_tc<128,128,2,4,1><<<dim3(8,8,32), 256>>>(
            sq, sq+HD, DD, (long)SS*DD, 64, sk, sk+HD, DD, (long)SS*DD, 64,
            sc, (bf16*)0, (bf16*)0, SS, (long)HH*SS*SS, (long)SS*SS,
            (float*)0, 0.125f, 0, 64);

        softmax_split<<<BB*HH*SS, 256>>>(sc, sP);

        gemm_tc<128,64,4,2,0><<<dim3(1,8,32), 256>>>(
            sP, sP+PHALF, SS, (long)HH*SS*SS, (long)SS*SS,
            sv, sv+HD, DD, (long)SS*DD, 64,
            (float*)0, sat, sat+HD, DD, (long)SS*DD, 64,
            (float*)0, 1.f, 0, SS);

        gemm_tc<128,128,2,4,0><<<dim3(8,16,1), 256>>>(
            sat, sat+HD, DD, 0,0, woh, wol, DD, 0,0,
            t2, (bf16*)0, (bf16*)0, DD, 0,0, bo + i*DD, 1.f, 0, DD);
        add_ln<<<MTOK, 256>>>(h, t2, g1 + i*DD, be1 + i*DD, sh);

        gemm_tc<128,128,2,4,0><<<dim3(32,16,1), 256>>>(
            sh, sh+HD, DD, 0,0, w1h, w1l, FFF, 0,0,
            (float*)0, st1, st1+TF, FFF, 0,0, b1f + i*FFF, 1.f, 1, DD);
        gemm_tc<128,128,2,4,0><<<dim3(8,16,1), 256>>>(
            st1, st1+TF, FFF, 0,0, w2h, w2l, DD, 0,0,
            t2, (bf16*)0, (bf16*)0, DD, 0,0, b2f + i*DD, 1.f, 0, FFF);
        add_ln<<<MTOK, 256>>>(h, t2, g2 + i*DD, be2 + i*DD, sh);
    }

    gemm_tc<128,128,2,4,0><<<dim3(250,16,1), 256>>>(
        sh, sh+HD, DD, 0,0, wout, wout + nO, VV, 0,0,
        out, (bf16*)0, (bf16*)0, VV, 0,0, bout, 1.f, 0, DD);
}

// round 6
// speedup vs baseline: 2.8613x; 1.0583x over previous
#include <cuda_runtime.h>
#include <cuda_bf16.h>
#include <math.h>
#include <stdint.h>

typedef __nv_bfloat16 bf16;

#define BB 2
#define SS 1024
#define DD 1024
#define HH 16
#define LL 3
#define FFF 4096
#define VV 32000
#define MTOK (BB*SS)
#define NQKV 3072
#define PHALF ((size_t)BB*HH*SS*SS)

// ------------------------- scratch -------------------------
__device__ float g_h[MTOK * DD];
__device__ float g_t2[MTOK * DD];
__device__ float g_scores[(size_t)BB * HH * SS * SS];
__device__ float g_bqkv[LL * NQKV];

__device__ bf16 s_h[2 * MTOK * DD];
__device__ bf16 s_qkv[2 * MTOK * NQKV];
__device__ bf16 s_attn[2 * MTOK * DD];
__device__ bf16 s_t1[2 * MTOK * FFF];
__device__ bf16 s_P[2 * PHALF];

__device__ bf16 s_wqkv[2 * LL * DD * NQKV];
__device__ bf16 s_wo[2 * LL * DD * DD];
__device__ bf16 s_w1[2 * LL * DD * FFF];
__device__ bf16 s_w2[2 * LL * FFF * DD];
__device__ bf16 s_wout[2 * DD * VV];

// ------------------------- helpers -------------------------
__device__ __forceinline__ uint32_t pack_hi2(float x, float y) {
    __nv_bfloat162 v = __halves2bfloat162(__float2bfloat16_rn(x), __float2bfloat16_rn(y));
    return *reinterpret_cast<uint32_t*>(&v);
}
__device__ __forceinline__ uint32_t pack_lo2(float x, float y) {
    float rx = x - __bfloat162float(__float2bfloat16_rn(x));
    float ry = y - __bfloat162float(__float2bfloat16_rn(y));
    __nv_bfloat162 v = __halves2bfloat162(__float2bfloat16_rn(rx), __float2bfloat16_rn(ry));
    return *reinterpret_cast<uint32_t*>(&v);
}
__device__ __forceinline__ uint32_t cvta_smem(const void* p) {
    return (uint32_t)__cvta_generic_to_shared(p);
}
__device__ __forceinline__ void cp16(uint32_t dst, const void* src) {
    asm volatile("cp.async.cg.shared.global [%0], [%1], 16;" :: "r"(dst), "l"(src) : "memory");
}
__device__ __forceinline__ void cp_commit() { asm volatile("cp.async.commit_group;" ::: "memory"); }
__device__ __forceinline__ void cp_wait0()  { asm volatile("cp.async.wait_group 0;" ::: "memory"); }
__device__ __forceinline__ void ldm4(uint32_t* r, uint32_t a) {
    asm volatile("ldmatrix.sync.aligned.m8n8.x4.shared.b16 {%0,%1,%2,%3}, [%4];"
                 : "=r"(r[0]), "=r"(r[1]), "=r"(r[2]), "=r"(r[3]) : "r"(a));
}
__device__ __forceinline__ void ldm4t(uint32_t* r, uint32_t a) {
    asm volatile("ldmatrix.sync.aligned.m8n8.x4.trans.shared.b16 {%0,%1,%2,%3}, [%4];"
                 : "=r"(r[0]), "=r"(r[1]), "=r"(r[2]), "=r"(r[3]) : "r"(a));
}
#define MMA_BF16(c, a, b)                                                     \
    asm volatile("mma.sync.aligned.m16n8k16.row.col.f32.bf16.bf16.f32 "       \
                 "{%0,%1,%2,%3}, {%4,%5,%6,%7}, {%8,%9}, {%0,%1,%2,%3};"      \
                 : "+f"(c[0]), "+f"(c[1]), "+f"(c[2]), "+f"(c[3])             \
                 : "r"(a[0]), "r"(a[1]), "r"(a[2]), "r"(a[3]),                \
                   "r"(b[0]), "r"(b[1]))

// ------------------------- split kernels -------------------------
__global__ void split_kernel(const float* __restrict__ in, bf16* __restrict__ out, int n)
{
    int i8 = (blockIdx.x * blockDim.x + threadIdx.x) * 8;
    if (i8 >= n) return;
    float4 a = *(const float4*)(in + i8);
    float4 b = *(const float4*)(in + i8 + 4);
    uint4 hi = {pack_hi2(a.x,a.y), pack_hi2(a.z,a.w), pack_hi2(b.x,b.y), pack_hi2(b.z,b.w)};
    uint4 lo = {pack_lo2(a.x,a.y), pack_lo2(a.z,a.w), pack_lo2(b.x,b.y), pack_lo2(b.z,b.w)};
    *(uint4*)(out + i8) = hi;
    *(uint4*)(out + n + i8) = lo;
}

// strided split: in [n/ldin][ldin] -> out planes with row stride ldout at coloff
__global__ void split_strided(const float* __restrict__ in, bf16* __restrict__ out_hi,
                              bf16* __restrict__ out_lo, int n, int ldin, int ldout, int coloff)
{
    int i8 = (blockIdx.x * blockDim.x + threadIdx.x) * 8;
    if (i8 >= n) return;
    int row = i8 / ldin, col = i8 % ldin;
    size_t o = (size_t)row * ldout + coloff + col;
    float4 a = *(const float4*)(in + i8);
    float4 b = *(const float4*)(in + i8 + 4);
    uint4 hi = {pack_hi2(a.x,a.y), pack_hi2(a.z,a.w), pack_hi2(b.x,b.y), pack_hi2(b.z,b.w)};
    uint4 lo = {pack_lo2(a.x,a.y), pack_lo2(a.z,a.w), pack_lo2(b.x,b.y), pack_lo2(b.z,b.w)};
    *(uint4*)(out_hi + o) = hi;
    *(uint4*)(out_lo + o) = lo;
}

__global__ void concat_bias(const float* __restrict__ bq, const float* __restrict__ bk,
                            const float* __restrict__ bv, float* __restrict__ out)
{
    int i = blockIdx.x * blockDim.x + threadIdx.x; // over LL*NQKV
    int l = i / NQKV, j = i % NQKV;
    float v = (j < DD) ? bq[l*DD + j] : (j < 2*DD) ? bk[l*DD + j - DD] : bv[l*DD + j - 2*DD];
    out[i] = v;
}

// ------------------------- embedding -------------------------
__global__ void embed_kernel(const int* __restrict__ x, const float* __restrict__ noise,
                             const float* __restrict__ emb, float* __restrict__ h,
                             bf16* __restrict__ sh)
{
    int i4 = (blockIdx.x * blockDim.x + threadIdx.x) * 4;
    int tok = i4 >> 10, d = i4 & 1023;
    float4 e = *(const float4*)(emb + (size_t)x[tok] * DD + d);
    float4 nz = *(const float4*)(noise + i4);
    float4 v = {e.x + 0.05f*nz.x, e.y + 0.05f*nz.y, e.z + 0.05f*nz.z, e.w + 0.05f*nz.w};
    *(float4*)(h + i4) = v;
    *(uint32_t*)(sh + i4)                 = pack_hi2(v.x, v.y);
    *(uint32_t*)(sh + i4 + 2)             = pack_hi2(v.z, v.w);
    *(uint32_t*)(sh + MTOK*DD + i4)       = pack_lo2(v.x, v.y);
    *(uint32_t*)(sh + MTOK*DD + i4 + 2)   = pack_lo2(v.z, v.w);
}

// ------------------------- tensor-core split GEMM, BK=32, 2-stage ----------
// A [M][K] hi/lo. BLAYOUT 0: B [K][N]; BLAYOUT 1: B [N][K] (BN=128).
// K % 32 == 0. Batched via blockIdx.z (zb=z>>4, zh=z&15).
template<int BM, int BN, int WARPS_M, int WARPS_N, int BLAYOUT>
__global__ __launch_bounds__(256, 2)
void gemm_tc(const bf16* __restrict__ Ahi, const bf16* __restrict__ Alo, int lda,
             long sAb, long sAh,
             const bf16* __restrict__ Bhi, const bf16* __restrict__ Blo, int ldb,
             long sBb, long sBh,
             float* __restrict__ Cf, bf16* __restrict__ Chi, bf16* __restrict__ Clo,
             int ldc, long sCb, long sCh,
             const float* __restrict__ bias, float alpha, int relu, int K)
{
    constexpr int WTM = BM / WARPS_M, WTN = BN / WARPS_N;
    constexpr int IT = WTM / 16, JT = WTN / 8;
    constexpr int BP16 = (BLAYOUT == 0 ? 16 * BN * 2 : BN * 16 * 2);
    constexpr int A_SZ = 16384;                    // 2 panels x (hi+lo) x 4KB
    constexpr int STAGE = A_SZ + 4 * BP16;

    extern __shared__ __align__(16) unsigned char smem[];

    const int tid = threadIdx.x;
    const int lane = tid & 31, wid = tid >> 5;
    const int wm = wid / WARPS_N, wn = wid % WARPS_N;
    const int bm = blockIdx.y * BM, bn = blockIdx.x * BN;
    const int z = blockIdx.z, zb = z >> 4, zh = z & 15;

    const bf16* gAh = Ahi + (size_t)zb * sAb + (size_t)zh * sAh;
    const bf16* gAl = Alo + (size_t)zb * sAb + (size_t)zh * sAh;
    const bf16* gBh = Bhi + (size_t)zb * sBb + (size_t)zh * sBh;
    const bf16* gBl = Blo + (size_t)zb * sBb + (size_t)zh * sBh;
    const uint32_t s0 = cvta_smem(smem);

    float acc[IT][JT][4] = {};
    const int KT = K / 32;

    auto load_stage = [&](int kt, int st) {
        uint32_t base = s0 + st * STAGE;
        {
            int m = tid >> 1, c = tid & 1;
            uint32_t aoff = m * 32 + ((c ^ ((m >> 2) & 1)) << 4);
#pragma unroll
            for (int p = 0; p < 2; p++) {
                size_t g = (size_t)(bm + m) * lda + kt * 32 + p * 16 + c * 8;
                cp16(base + p * 8192 + aoff, gAh + g);
                cp16(base + p * 8192 + 4096 + aoff, gAl + g);
            }
        }
        if (BLAYOUT == 0) {
            constexpr int CPR = BN / 8;
            constexpr int TOT = 16 * CPR;
            if (TOT == 256 || tid < TOT) {
                int k = tid / CPR, c = tid % CPR;
                uint32_t boff = k * (BN * 2) + ((c ^ (k & 7)) << 4);
#pragma unroll
                for (int p = 0; p < 2; p++) {
                    size_t g = (size_t)(kt * 32 + p * 16 + k) * ldb + bn + c * 8;
                    cp16(base + A_SZ + p * 2 * BP16 + boff, gBh + g);
                    cp16(base + A_SZ + p * 2 * BP16 + BP16 + boff, gBl + g);
                }
            }
        } else {
            int n_ = tid >> 1, c = tid & 1;
            uint32_t boff = n_ * 32 + ((c ^ ((n_ >> 2) & 1)) << 4);
#pragma unroll
            for (int p = 0; p < 2; p++) {
                size_t g = (size_t)(bn + n_) * ldb + kt * 32 + p * 16 + c * 8;
                cp16(base + A_SZ + p * 2 * BP16 + boff, gBh + g);
                cp16(base + A_SZ + p * 2 * BP16 + BP16 + boff, gBl + g);
            }
        }
        cp_commit();
    };

    load_stage(0, 0);
    const int q8 = lane >> 3, r8 = lane & 7;

    for (int kt = 0; kt < KT; kt++) {
        cp_wait0();
        __syncthreads();
        if (kt + 1 < KT) load_stage(kt + 1, (kt + 1) & 1);

        uint32_t st = s0 + (kt & 1) * STAGE;
#pragma unroll
        for (int ksl = 0; ksl < 2; ksl++) {
            uint32_t sa_hi = st + ksl * 8192;
            uint32_t sa_lo = sa_hi + 4096;
            uint32_t sb_hi = st + A_SZ + ksl * 2 * BP16;
            uint32_t sb_lo = sb_hi + BP16;

            uint32_t ah[IT][4], al[IT][4];
#pragma unroll
            for (int i = 0; i < IT; i++) {
                int row = wm * WTM + i * 16 + ((q8 & 1) << 3) + r8;
                int c = q8 >> 1;
                uint32_t off = row * 32 + ((c ^ ((row >> 2) & 1)) << 4);
                ldm4(ah[i], sa_hi + off);
                ldm4(al[i], sa_lo + off);
            }
            uint32_t bh[JT][2], bl[JT][2];
            if (BLAYOUT == 1) {
#pragma unroll
                for (int jj = 0; jj < JT / 2; jj++) {
                    int row = wn * WTN + jj * 16 + ((q8 & 1) << 3) + r8;
                    int c = q8 >> 1;
                    uint32_t off = row * 32 + ((c ^ ((row >> 2) & 1)) << 4);
                    uint32_t r[4];
                    ldm4(r, sb_hi + off);
                    bh[2*jj][0] = r[0]; bh[2*jj+1][0] = r[1];
                    bh[2*jj][1] = r[2]; bh[2*jj+1][1] = r[3];
                    ldm4(r, sb_lo + off);
                    bl[2*jj][0] = r[0]; bl[2*jj+1][0] = r[1];
                    bl[2*jj][1] = r[2]; bl[2*jj+1][1] = r[3];
                }
            } else {
#pragma unroll
                for (int jj = 0; jj < JT / 2; jj++) {
                    int krow = ((q8 & 1) << 3) + r8;
                    int c = (wn * WTN + jj * 16) / 8 + (q8 >> 1);
                    uint32_t off = krow * (BN * 2) + ((c ^ (krow & 7)) << 4);
                    uint32_t r[4];
                    ldm4t(r, sb_hi + off);
                    bh[2*jj][0] = r[0]; bh[2*jj][1] = r[1];
                    bh[2*jj+1][0] = r[2]; bh[2*jj+1][1] = r[3];
                    ldm4t(r, sb_lo + off);
                    bl[2*jj][0] = r[0]; bl[2*jj][1] = r[1];
                    bl[2*jj+1][0] = r[2]; bl[2*jj+1][1] = r[3];
                }
            }
#pragma unroll
            for (int i = 0; i < IT; i++)
#pragma unroll
                for (int j = 0; j < JT; j++) {
                    MMA_BF16(acc[i][j], ah[i], bh[j]);
                    MMA_BF16(acc[i][j], ah[i], bl[j]);
                    MMA_BF16(acc[i][j], al[i], bh[j]);
                }
        }
    }

    float* pCf = Cf ? Cf + (size_t)zb * sCb + (size_t)zh * sCh : (float*)0;
    bf16* pChi = Chi ? Chi + (size_t)zb * sCb + (size_t)zh * sCh : (bf16*)0;
    bf16* pClo = Clo ? Clo + (size_t)zb * sCb + (size_t)zh * sCh : (bf16*)0;
    const int grp = lane >> 2, qp = (lane & 3) << 1;
#pragma unroll
    for (int i = 0; i < IT; i++) {
        int r0 = bm + wm * WTM + i * 16 + grp;
#pragma unroll
        for (int j = 0; j < JT; j++) {
            int n0 = bn + wn * WTN + j * 8 + qp;
            float b0 = 0.f, b1 = 0.f;
            if (bias) { b0 = __ldg(bias + n0); b1 = __ldg(bias + n0 + 1); }
            float v00 = (acc[i][j][0] + b0) * alpha;
            float v01 = (acc[i][j][1] + b1) * alpha;
            float v10 = (acc[i][j][2] + b0) * alpha;
            float v11 = (acc[i][j][3] + b1) * alpha;
            if (relu) {
                v00 = fmaxf(v00, 0.f); v01 = fmaxf(v01, 0.f);
                v10 = fmaxf(v10, 0.f); v11 = fmaxf(v11, 0.f);
            }
            size_t o0 = (size_t)r0 * ldc + n0;
            size_t o1 = (size_t)(r0 + 8) * ldc + n0;
            if (pCf) {
                float2 a = {v00, v01}, b = {v10, v11};
                *(float2*)(pCf + o0) = a;
                *(float2*)(pCf + o1) = b;
            }
            if (pChi) {
                *(uint32_t*)(pChi + o0) = pack_hi2(v00, v01);
                *(uint32_t*)(pClo + o0) = pack_lo2(v00, v01);
                *(uint32_t*)(pChi + o1) = pack_hi2(v10, v11);
                *(uint32_t*)(pClo + o1) = pack_lo2(v10, v11);
            }
        }
    }
}

// ------------------------- softmax (empathy bias cancels) -------------------
__global__ void softmax_split(const float* __restrict__ Sc, bf16* __restrict__ P)
{
    const float* p = Sc + (size_t)blockIdx.x * SS;
    size_t ob = (size_t)blockIdx.x * SS + threadIdx.x * 4;
    const int tid = threadIdx.x;
    __shared__ float red[8];

    float4 x = *(const float4*)(p + tid * 4);
    float m = fmaxf(fmaxf(x.x, x.y), fmaxf(x.z, x.w));
#pragma unroll
    for (int o = 16; o; o >>= 1) m = fmaxf(m, __shfl_xor_sync(0xffffffffu, m, o));
    if ((tid & 31) == 0) red[tid >> 5] = m;
    __syncthreads();
    float bm = red[0];
#pragma unroll
    for (int i = 1; i < 8; i++) bm = fmaxf(bm, red[i]);
    __syncthreads();
    x.x = expf(x.x - bm); x.y = expf(x.y - bm);
    x.z = expf(x.z - bm); x.w = expf(x.w - bm);
    float s = x.x + x.y + x.z + x.w;
#pragma unroll
    for (int o = 16; o; o >>= 1) s += __shfl_xor_sync(0xffffffffu, s, o);
    if ((tid & 31) == 0) red[tid >> 5] = s;
    __syncthreads();
    float bs = 0.f;
#pragma unroll
    for (int i = 0; i < 8; i++) bs += red[i];
    float inv = 1.0f / bs;
    x.x *= inv; x.y *= inv; x.z *= inv; x.w *= inv;
    *(uint32_t*)(P + ob)             = pack_hi2(x.x, x.y);
    *(uint32_t*)(P + ob + 2)         = pack_hi2(x.z, x.w);
    *(uint32_t*)(P + PHALF + ob)     = pack_lo2(x.x, x.y);
    *(uint32_t*)(P + PHALF + ob + 2) = pack_lo2(x.z, x.w);
}

// ------------------------- residual + LayerNorm (+split) --------------------
__global__ void add_ln(float* __restrict__ h, const float* __restrict__ y,
                       const float* __restrict__ g, const float* __restrict__ be,
                       bf16* __restrict__ sh)
{
    float* hr = h + (size_t)blockIdx.x * DD;
    const float* yr = y + (size_t)blockIdx.x * DD;
    const int tid = threadIdx.x;
    __shared__ float red[8];

    float4 hv = *(float4*)(hr + tid * 4);
    float4 yv = *(const float4*)(yr + tid * 4);
    float z[4] = {hv.x + yv.x, hv.y + yv.y, hv.z + yv.z, hv.w + yv.w};

    float s = z[0] + z[1] + z[2] + z[3];
#pragma unroll
    for (int o = 16; o; o >>= 1) s += __shfl_xor_sync(0xffffffffu, s, o);
    if ((tid & 31) == 0) red[tid >> 5] = s;
    __syncthreads();
    float tot = 0.f;
#pragma unroll
    for (int i = 0; i < 8; i++) tot += red[i];
    float mean = tot * (1.0f / DD);
    __syncthreads();

    float d0 = z[0]-mean, d1 = z[1]-mean, d2 = z[2]-mean, d3 = z[3]-mean;
    float vs = d0*d0 + d1*d1 + d2*d2 + d3*d3;
#pragma unroll
    for (int o = 16; o; o >>= 1) vs += __shfl_xor_sync(0xffffffffu, vs, o);
    if ((tid & 31) == 0) red[tid >> 5] = vs;
    __syncthreads();
    float vtot = 0.f;
#pragma unroll
    for (int i = 0; i < 8; i++) vtot += red[i];
    float rstd = rsqrtf(vtot * (1.0f / DD) + 1e-5f);

    float4 gv = *(const float4*)(g + tid * 4);
    float4 bv = *(const float4*)(be + tid * 4);
    float4 o;
    o.x = d0*rstd*gv.x + bv.x; o.y = d1*rstd*gv.y + bv.y;
    o.z = d2*rstd*gv.z + bv.z; o.w = d3*rstd*gv.w + bv.w;
    *(float4*)(hr + tid * 4) = o;

    size_t ob = (size_t)blockIdx.x * DD + tid * 4;
    *(uint32_t*)(sh + ob)               = pack_hi2(o.x, o.y);
    *(uint32_t*)(sh + ob + 2)           = pack_hi2(o.z, o.w);
    *(uint32_t*)(sh + MTOK*DD + ob)     = pack_lo2(o.x, o.y);
    *(uint32_t*)(sh + MTOK*DD + ob + 2) = pack_lo2(o.z, o.w);
}

// ------------------------- launch -------------------------
extern "C" void kernel_launch(void* const* d_in, const int* in_sizes, int n_in,
                              void* d_out, int out_size)
{
    const int*   x     = (const int*)d_in[0];
    const float* noise = (const float*)d_in[1];
    const float* emb   = (const float*)d_in[2];
    const float* Wq    = (const float*)d_in[3];
    const float* bq    = (const float*)d_in[4];
    const float* Wk    = (const float*)d_in[5];
    const float* bk    = (const float*)d_in[6];
    const float* Wv    = (const float*)d_in[7];
    const float* bv    = (const float*)d_in[8];
    const float* Wo    = (const float*)d_in[9];
    const float* bo    = (const float*)d_in[10];
    const float* W1f   = (const float*)d_in[11];
    const float* b1f   = (const float*)d_in[12];
    const float* W2f   = (const float*)d_in[13];
    const float* b2f   = (const float*)d_in[14];
    const float* g1    = (const float*)d_in[15];
    const float* be1   = (const float*)d_in[16];
    const float* g2    = (const float*)d_in[17];
    const float* be2   = (const float*)d_in[18];
    const float* Wout  = (const float*)d_in[19];
    const float* bout  = (const float*)d_in[20];
    float* out = (float*)d_out;

    float *h, *t2, *sc, *bqkv;
    bf16 *sh, *sqkv, *sat, *st1, *sP;
    bf16 *wqkv, *wo, *w1, *w2, *wout;
    cudaGetSymbolAddress((void**)&h, g_h);
    cudaGetSymbolAddress((void**)&t2, g_t2);
    cudaGetSymbolAddress((void**)&sc, g_scores);
    cudaGetSymbolAddress((void**)&bqkv, g_bqkv);
    cudaGetSymbolAddress((void**)&sh, s_h);
    cudaGetSymbolAddress((void**)&sqkv, s_qkv);
    cudaGetSymbolAddress((void**)&sat, s_attn);
    cudaGetSymbolAddress((void**)&st1, s_t1);
    cudaGetSymbolAddress((void**)&sP, s_P);
    cudaGetSymbolAddress((void**)&wqkv, s_wqkv);
    cudaGetSymbolAddress((void**)&wo, s_wo);
    cudaGetSymbolAddress((void**)&w1, s_w1);
    cudaGetSymbolAddress((void**)&w2, s_w2);
    cudaGetSymbolAddress((void**)&wout, s_wout);

    // raise dynamic smem limits (64KB / 64KB / 48KB)
    cudaFuncSetAttribute((const void*)gemm_tc<128,128,2,4,0>,
                         cudaFuncAttributeMaxDynamicSharedMemorySize, 65536);
    cudaFuncSetAttribute((const void*)gemm_tc<128,128,2,4,1>,
                         cudaFuncAttributeMaxDynamicSharedMemorySize, 65536);
    cudaFuncSetAttribute((const void*)gemm_tc<128,64,4,2,0>,
                         cudaFuncAttributeMaxDynamicSharedMemorySize, 49152);
    const int SM0 = 65536, SM1 = 65536, SM2 = 49152;

    const int nQ = LL * DD * DD;
    const int nF = LL * DD * FFF;
    const int nO = DD * VV;
    const long WQKV_PLANE = (long)LL * DD * NQKV;

    // weight splits
    for (int l = 0; l < LL; l++) {
        bf16* oh = wqkv + (size_t)l * DD * NQKV;
        bf16* ol = oh + WQKV_PLANE;
        split_strided<<<DD*DD/2048, 256>>>(Wq + (size_t)l*DD*DD, oh, ol, DD*DD, DD, NQKV, 0);
        split_strided<<<DD*DD/2048, 256>>>(Wk + (size_t)l*DD*DD, oh, ol, DD*DD, DD, NQKV, DD);
        split_strided<<<DD*DD/2048, 256>>>(Wv + (size_t)l*DD*DD, oh, ol, DD*DD, DD, NQKV, 2*DD);
    }
    split_kernel<<<nQ/2048, 256>>>(Wo, wo, nQ);
    split_kernel<<<nF/2048, 256>>>(W1f, w1, nF);
    split_kernel<<<nF/2048, 256>>>(W2f, w2, nF);
    split_kernel<<<nO/2048, 256>>>(Wout, wout, nO);
    concat_bias<<<LL*NQKV/256, 256>>>(bq, bk, bv, bqkv);

    embed_kernel<<<(MTOK * DD) / 1024, 256>>>(x, noise, emb, h, sh);

    const long HD = (long)MTOK * DD;
    const long QP = (long)MTOK * NQKV;   // qkv plane
    const long TF = (long)MTOK * FFF;

    for (int i = 0; i < LL; i++) {
        const bf16 *wqkvh = wqkv + (size_t)i * DD * NQKV, *wqkvl = wqkvh + WQKV_PLANE;
        const bf16 *woh = wo + (size_t)i * DD * DD, *wol = woh + nQ;
        const bf16 *w1h = w1 + (size_t)i * DD * FFF, *w1l = w1h + nF;
        const bf16 *w2h = w2 + (size_t)i * FFF * DD, *w2l = w2h + nF;

        // fused QKV: [2048 x 3072] = h @ Wqkv
        gemm_tc<128,128,2,4,0><<<dim3(NQKV/128, 16, 1), 256, SM0>>>(
            sh, sh+HD, DD, 0,0, wqkvh, wqkvl, NQKV, 0,0,
            (float*)0, sqkv, sqkv+QP, NQKV, 0,0, bqkv + i*NQKV, 1.f, 0, DD);

        // scores = 0.125 * Q K^T  (Q at col 0, K at col 1024 of sqkv)
        gemm_tc<128,128,2,4,1><<<dim3(8,8,32), 256, SM1>>>(
            sqkv, sqkv+QP, NQKV, (long)SS*NQKV, 64,
            sqkv+DD, sqkv+QP+DD, NQKV, (long)SS*NQKV, 64,
            sc, (bf16*)0, (bf16*)0, SS, (long)HH*SS*SS, (long)SS*SS,
            (float*)0, 0.125f, 0, 64);

        softmax_split<<<BB*HH*SS, 256>>>(sc, sP);

        // attn = P V  (V at col 2048)
        gemm_tc<128,64,4,2,0><<<dim3(1,8,32), 256, SM2>>>(
            sP, sP+PHALF, SS, (long)HH*SS*SS, (long)SS*SS,
            sqkv+2*DD, sqkv+QP+2*DD, NQKV, (long)SS*NQKV, 64,
            (float*)0, sat, sat+HD, DD, (long)SS*DD, 64,
            (float*)0, 1.f, 0, SS);

        gemm_tc<128,128,2,4,0><<<dim3(8,16,1), 256, SM0>>>(
            sat, sat+HD, DD, 0,0, woh, wol, DD, 0,0,
            t2, (bf16*)0, (bf16*)0, DD, 0,0, bo + i*DD, 1.f, 0, DD);
        add_ln<<<MTOK, 256>>>(h, t2, g1 + i*DD, be1 + i*DD, sh);

        gemm_tc<128,128,2,4,0><<<dim3(32,16,1), 256, SM0>>>(
            sh, sh+HD, DD, 0,0, w1h, w1l, FFF, 0,0,
            (float*)0, st1, st1+TF, FFF, 0,0, b1f + i*FFF, 1.f, 1, DD);
        gemm_tc<128,128,2,4,0><<<dim3(8,16,1), 256, SM0>>>(
            st1, st1+TF, FFF, 0,0, w2h, w2l, DD, 0,0,
            t2, (bf16*)0, (bf16*)0, DD, 0,0, b2f + i*DD, 1.f, 0, FFF);
        add_ln<<<MTOK, 256>>>(h, t2, g2 + i*DD, be2 + i*DD, sh);
    }

    gemm_tc<128,128,2,4,0><<<dim3(VV/128, 16, 1), 256, SM0>>>(
        sh, sh+HD, DD, 0,0, wout, wout + nO, VV, 0,0,
        out, (bf16*)0, (bf16*)0, VV, 0,0, bout, 1.f, 0, DD);
}